// round 1
// baseline (speedup 1.0000x reference)
#include <cuda_runtime.h>

// Problem constants (fixed shapes per reference)
#define BB   8
#define SS   2048
#define KIN  512
#define NIN  2048
#define NP   4096
#define HID  4096
#define DM   1024
#define KSEL 256

typedef unsigned long long ull;

// ---------------- scratch (static device globals; no allocation) ----------------
__device__ float    g_cwT[(size_t)NIN * NP];        // 32 MB  combination_weights^T [n][p]
__device__ float    g_pa[(size_t)BB * SS * NP];     // 256 MB process_activations  [b][s][p]
__device__ float    g_pasel[(size_t)BB * SS * KSEL];// 16 MB  gathered top-k pa     [b][s][j]
__device__ float    g_mask[BB * NIN];               // input selection mask
__device__ float    g_h[BB * HID];                  // MLP hidden
__device__ unsigned g_scoreEnc[BB * NP];            // encoded max-over-s scores
__device__ float    g_fscore[BB * NP];              // final router scores
__device__ int      g_pidx[BB * KSEL];              // selected process indices

// ---------------- helpers ----------------
__device__ __forceinline__ unsigned fenc(float f) {
    unsigned u = __float_as_uint(f);
    return (u & 0x80000000u) ? ~u : (u | 0x80000000u);
}
__device__ __forceinline__ float fdec(unsigned u) {
    return __uint_as_float((u & 0x80000000u) ? (u & 0x7fffffffu) : ~u);
}
__device__ __forceinline__ float gelu_f(float x) {
    return 0.5f * x * (1.0f + erff(x * 0.70710678118654752f));
}
__device__ __forceinline__ ull pack2(float x, float y) {
    ull r; asm("mov.b64 %0, {%1, %2};" : "=l"(r) : "f"(x), "f"(y)); return r;
}
__device__ __forceinline__ float2 unpack2(ull v) {
    float2 r; asm("mov.b64 {%0, %1}, %2;" : "=f"(r.x), "=f"(r.y) : "l"(v)); return r;
}
// packed dual-FMA: c.xy += a.xy * b.xy  (sm_103a FFMA2 — only reachable via PTX)
__device__ __forceinline__ void fma2(ull& c, ull a, ull b) {
    asm("fma.rn.f32x2 %0, %1, %2, %0;" : "+l"(c) : "l"(a), "l"(b));
}

union F4U { float4 f; ull u[2]; };

// ---------------- K0: init mask + score buffers ----------------
__global__ void k_init() {
    int t = blockIdx.x * blockDim.x + threadIdx.x;
    if (t < BB * NIN) g_mask[t] = 0.0f;
    if (t < BB * NP)  g_scoreEnc[t] = 0u;
}

__global__ void k_scatter(const int* __restrict__ sidx) {
    int t = blockIdx.x * blockDim.x + threadIdx.x;
    if (t < BB * KIN) {
        int b = t >> 9;               // KIN = 512
        g_mask[b * NIN + sidx[t]] = 1.0f;
    }
}

// ---------------- K0a: transpose combination_weights [NP,NIN] -> [NIN,NP] ----------------
__global__ void k_transpose(const float* __restrict__ cw) {
    __shared__ float t[32][33];
    int nb = blockIdx.x * 32, pb = blockIdx.y * 32;
    int tx = threadIdx.x, ty = threadIdx.y;
#pragma unroll
    for (int i = 0; i < 32; i += 8)
        t[ty + i][tx] = cw[(size_t)(pb + ty + i) * NIN + nb + tx];
    __syncthreads();
#pragma unroll
    for (int i = 0; i < 32; i += 8)
        g_cwT[(size_t)(nb + ty + i) * NP + pb + tx] = t[tx][ty + i];
}

// ---------------- K1: gathered GEMM1 + GELU + column max ----------------
// C[s,p] = gelu( sum_k A[s,k] * cwT[idx[b,k], p] ), also scores[b,p] = max_s C
__global__ __launch_bounds__(256, 2)
void k_gemm1(const float* __restrict__ act, const int* __restrict__ sidx) {
    const int b  = blockIdx.z;
    const int p0 = blockIdx.x * 128;
    const int s0 = blockIdx.y * 128;
    const float* Ab   = act  + (size_t)b * SS * KIN;
    const int*   idxb = sidx + b * KIN;

    __shared__ float As[16][132];  // [kk][m], padded to reduce store conflicts
    __shared__ float Bs[16][128];  // [kk][n]

    const int tid = threadIdx.x;
    const int tm = tid >> 4, tn = tid & 15;

    ull acc[8][4];
#pragma unroll
    for (int r = 0; r < 8; r++)
#pragma unroll
        for (int c = 0; c < 4; c++) acc[r][c] = 0ULL;

    for (int k0 = 0; k0 < KIN; k0 += 16) {
        // A tile 128x16, store transposed into As[kk][m]
#pragma unroll
        for (int q = 0; q < 2; q++) {
            int f = tid + q * 256;
            int row = f >> 2, c4 = f & 3;
            float4 v = *(const float4*)(Ab + (size_t)(s0 + row) * KIN + k0 + c4 * 4);
            As[c4 * 4 + 0][row] = v.x; As[c4 * 4 + 1][row] = v.y;
            As[c4 * 4 + 2][row] = v.z; As[c4 * 4 + 3][row] = v.w;
        }
        // B tile 16x128: row kk comes from cwT[idx[b,k0+kk]]
#pragma unroll
        for (int q = 0; q < 2; q++) {
            int f = tid + q * 256;
            int kk = f >> 5, c4 = f & 31;
            int n = idxb[k0 + kk];
            *(float4*)&Bs[kk][c4 * 4] =
                *(const float4*)(g_cwT + (size_t)n * NP + p0 + c4 * 4);
        }
        __syncthreads();
#pragma unroll
        for (int kk = 0; kk < 16; ++kk) {
            F4U a0, a1, b0, b1;
            a0.f = *(const float4*)&As[kk][tm * 8];
            a1.f = *(const float4*)&As[kk][tm * 8 + 4];
            b0.f = *(const float4*)&Bs[kk][tn * 8];
            b1.f = *(const float4*)&Bs[kk][tn * 8 + 4];
            ull bb[4] = { b0.u[0], b0.u[1], b1.u[0], b1.u[1] };
            ull aa[8];
            aa[0] = pack2(a0.f.x, a0.f.x); aa[1] = pack2(a0.f.y, a0.f.y);
            aa[2] = pack2(a0.f.z, a0.f.z); aa[3] = pack2(a0.f.w, a0.f.w);
            aa[4] = pack2(a1.f.x, a1.f.x); aa[5] = pack2(a1.f.y, a1.f.y);
            aa[6] = pack2(a1.f.z, a1.f.z); aa[7] = pack2(a1.f.w, a1.f.w);
#pragma unroll
            for (int r = 0; r < 8; r++)
#pragma unroll
                for (int c = 0; c < 4; c++) fma2(acc[r][c], aa[r], bb[c]);
        }
        __syncthreads();
    }

    // epilogue: GELU, store pa, column max
    float vals[8][8];
#pragma unroll
    for (int r = 0; r < 8; r++)
#pragma unroll
        for (int c = 0; c < 4; c++) {
            float2 v = unpack2(acc[r][c]);
            vals[r][2 * c]     = gelu_f(v.x);
            vals[r][2 * c + 1] = gelu_f(v.y);
        }
#pragma unroll
    for (int r = 0; r < 8; r++) {
        int s = s0 + tm * 8 + r;
        float* po = g_pa + ((size_t)b * SS + s) * NP + p0 + tn * 8;
        *(float4*)po       = make_float4(vals[r][0], vals[r][1], vals[r][2], vals[r][3]);
        *(float4*)(po + 4) = make_float4(vals[r][4], vals[r][5], vals[r][6], vals[r][7]);
    }
    __shared__ unsigned smax[128];
    if (tid < 128) smax[tid] = 0u;
    __syncthreads();
#pragma unroll
    for (int c = 0; c < 8; c++) {
        float m = vals[0][c];
#pragma unroll
        for (int r = 1; r < 8; r++) m = fmaxf(m, vals[r][c]);
        atomicMax(&smax[tn * 8 + c], fenc(m));
    }
    __syncthreads();
    if (tid < 128) atomicMax(&g_scoreEnc[b * NP + p0 + tid], smax[tid]);
}

// ---------------- K2: h[b,j] = gelu( sum_n mask[b,n]*w1[j,n] + b1[j] ) ----------------
__global__ void k_hidden(const float* __restrict__ w1, const float* __restrict__ b1) {
    int j = blockIdx.x;
    int tid = threadIdx.x;
    const float* wr = w1 + (size_t)j * NIN;
    float acc[BB];
#pragma unroll
    for (int b = 0; b < BB; b++) acc[b] = 0.0f;
    for (int n = tid; n < NIN; n += 256) {
        float w = wr[n];
#pragma unroll
        for (int b = 0; b < BB; b++) acc[b] += w * g_mask[b * NIN + n];
    }
    __shared__ float red[BB][256];
#pragma unroll
    for (int b = 0; b < BB; b++) red[b][tid] = acc[b];
    __syncthreads();
    for (int s1 = 128; s1 > 0; s1 >>= 1) {
        if (tid < s1) {
#pragma unroll
            for (int b = 0; b < BB; b++) red[b][tid] += red[b][tid + s1];
        }
        __syncthreads();
    }
    if (tid < BB) g_h[tid * HID + j] = gelu_f(red[tid][0] + b1[j]);
}

// ---------------- K3: relevance + final scores ----------------
__global__ void k_rel(const float* __restrict__ w2, const float* __restrict__ b2) {
    int warp = threadIdx.x >> 5, lane = threadIdx.x & 31;
    int p = blockIdx.x * 8 + warp;
    const float* wr = w2 + (size_t)p * HID;
    float acc[BB];
#pragma unroll
    for (int b = 0; b < BB; b++) acc[b] = 0.0f;
    for (int j = lane; j < HID; j += 32) {
        float w = wr[j];
#pragma unroll
        for (int b = 0; b < BB; b++) acc[b] += w * g_h[b * HID + j];
    }
#pragma unroll
    for (int o = 16; o > 0; o >>= 1)
#pragma unroll
        for (int b = 0; b < BB; b++) acc[b] += __shfl_down_sync(0xffffffffu, acc[b], o);
    if (lane == 0) {
#pragma unroll
        for (int b = 0; b < BB; b++) {
            float rel = acc[b] + b2[p];
            float sig = 1.0f / (1.0f + expf(-rel));
            g_fscore[b * NP + p] = fdec(g_scoreEnc[b * NP + p]) * sig;
        }
    }
}

// ---------------- K4: per-batch top-256 via bitonic sort of 4096 ----------------
__global__ void k_topk() {
    __shared__ ull key[NP];
    int b = blockIdx.x, tid = threadIdx.x;
    for (int i = tid; i < NP; i += 512)
        key[i] = ((ull)fenc(g_fscore[b * NP + i]) << 32) | (unsigned)i;
    __syncthreads();
    for (int k = 2; k <= NP; k <<= 1) {
        for (int j = k >> 1; j > 0; j >>= 1) {
            for (int i = tid; i < NP; i += 512) {
                int ix = i ^ j;
                if (ix > i) {
                    ull x = key[i], y = key[ix];
                    bool desc = ((i & k) == 0);
                    if (desc ? (x < y) : (x > y)) { key[i] = y; key[ix] = x; }
                }
            }
            __syncthreads();
        }
    }
    if (tid < KSEL) g_pidx[b * KSEL + tid] = (int)(key[tid] & 0xffffffffu);
}

// ---------------- K5a: gather pa columns for selected processes ----------------
__global__ void k_gather() {
    int blk = blockIdx.x;               // b*SS + s
    int b = blk >> 11, s = blk & (SS - 1);
    int j = threadIdx.x;                // 256 threads = KSEL
    int p = g_pidx[b * KSEL + j];
    g_pasel[((size_t)b * SS + s) * KSEL + j] = g_pa[((size_t)b * SS + s) * NP + p];
}

// ---------------- K5b: final GEMM: out = pa_sel @ proj[pidx] ----------------
__global__ __launch_bounds__(256, 2)
void k_gemm3(const float* __restrict__ proj, float* __restrict__ out) {
    const int b  = blockIdx.z;
    const int d0 = blockIdx.x * 128;
    const int s0 = blockIdx.y * 128;
    const float* Ab   = g_pasel + (size_t)b * SS * KSEL;
    const int*   idxb = g_pidx  + b * KSEL;

    __shared__ float As[16][132];
    __shared__ float Bs[16][128];

    const int tid = threadIdx.x;
    const int tm = tid >> 4, tn = tid & 15;

    ull acc[8][4];
#pragma unroll
    for (int r = 0; r < 8; r++)
#pragma unroll
        for (int c = 0; c < 4; c++) acc[r][c] = 0ULL;

    for (int k0 = 0; k0 < KSEL; k0 += 16) {
#pragma unroll
        for (int q = 0; q < 2; q++) {
            int f = tid + q * 256;
            int row = f >> 2, c4 = f & 3;
            float4 v = *(const float4*)(Ab + (size_t)(s0 + row) * KSEL + k0 + c4 * 4);
            As[c4 * 4 + 0][row] = v.x; As[c4 * 4 + 1][row] = v.y;
            As[c4 * 4 + 2][row] = v.z; As[c4 * 4 + 3][row] = v.w;
        }
#pragma unroll
        for (int q = 0; q < 2; q++) {
            int f = tid + q * 256;
            int kk = f >> 5, c4 = f & 31;
            int n = idxb[k0 + kk];
            *(float4*)&Bs[kk][c4 * 4] =
                *(const float4*)(proj + (size_t)n * DM + d0 + c4 * 4);
        }
        __syncthreads();
#pragma unroll
        for (int kk = 0; kk < 16; ++kk) {
            F4U a0, a1, b0, b1;
            a0.f = *(const float4*)&As[kk][tm * 8];
            a1.f = *(const float4*)&As[kk][tm * 8 + 4];
            b0.f = *(const float4*)&Bs[kk][tn * 8];
            b1.f = *(const float4*)&Bs[kk][tn * 8 + 4];
            ull bb[4] = { b0.u[0], b0.u[1], b1.u[0], b1.u[1] };
            ull aa[8];
            aa[0] = pack2(a0.f.x, a0.f.x); aa[1] = pack2(a0.f.y, a0.f.y);
            aa[2] = pack2(a0.f.z, a0.f.z); aa[3] = pack2(a0.f.w, a0.f.w);
            aa[4] = pack2(a1.f.x, a1.f.x); aa[5] = pack2(a1.f.y, a1.f.y);
            aa[6] = pack2(a1.f.z, a1.f.z); aa[7] = pack2(a1.f.w, a1.f.w);
#pragma unroll
            for (int r = 0; r < 8; r++)
#pragma unroll
                for (int c = 0; c < 4; c++) fma2(acc[r][c], aa[r], bb[c]);
        }
        __syncthreads();
    }
#pragma unroll
    for (int r = 0; r < 8; r++) {
        int s = s0 + tm * 8 + r;
        float* po = out + ((size_t)b * SS + s) * DM + d0 + tn * 8;
        float2 v0 = unpack2(acc[r][0]), v1 = unpack2(acc[r][1]);
        float2 v2 = unpack2(acc[r][2]), v3 = unpack2(acc[r][3]);
        *(float4*)po       = make_float4(v0.x, v0.y, v1.x, v1.y);
        *(float4*)(po + 4) = make_float4(v2.x, v2.y, v3.x, v3.y);
    }
}

// ---------------- entry ----------------
extern "C" void kernel_launch(void* const* d_in, const int* in_sizes, int n_in,
                              void* d_out, int out_size) {
    const float* act  = (const float*)d_in[0];
    const int*   sidx = (const int*)d_in[1];
    // d_in[2] is the scalar k (=256) when present; detect and skip it.
    int o = (n_in >= 9 && in_sizes[2] == 1) ? 3 : 2;
    const float* cw   = (const float*)d_in[o + 0];
    const float* proj = (const float*)d_in[o + 1];
    const float* w1   = (const float*)d_in[o + 2];
    const float* b1   = (const float*)d_in[o + 3];
    const float* w2   = (const float*)d_in[o + 4];
    const float* b2   = (const float*)d_in[o + 5];
    float* out = (float*)d_out;

    k_init<<<(BB * NP + 255) / 256, 256>>>();
    k_scatter<<<(BB * KIN + 255) / 256, 256>>>(sidx);
    k_transpose<<<dim3(NIN / 32, NP / 32), dim3(32, 8)>>>(cw);
    k_gemm1<<<dim3(NP / 128, SS / 128, BB), 256>>>(act, sidx);
    k_hidden<<<HID, 256>>>(w1, b1);
    k_rel<<<NP / 8, 256>>>(w2, b2);
    k_topk<<<BB, 512>>>();
    k_gather<<<BB * SS, 256>>>();
    k_gemm3<<<dim3(DM / 128, SS / 128, BB), 256>>>(proj, out);
}

// round 3
// speedup vs baseline: 1.7734x; 1.7734x over previous
#include <cuda_runtime.h>
#include <cuda_bf16.h>

#define BB   8
#define SS   2048
#define KIN  512
#define NIN  2048
#define NP   4096
#define HID  4096
#define DM   1024
#define KSEL 256

typedef unsigned long long ull;
typedef unsigned int u32;

// ---------------- scratch (static device globals; no allocation) ----------------
__device__ __align__(256) __nv_bfloat16 g_Asp[(size_t)BB * 2 * SS * KIN];  // 32 MB A splits
__device__ __align__(256) __nv_bfloat16 g_Bsp[(size_t)BB * 2 * NP * KIN];  // 64 MB B splits
__device__ __align__(256) float g_pasel[(size_t)BB * SS * KSEL];           // 16 MB
__device__ float    g_mask[BB * NIN];
__device__ float    g_h[BB * HID];
__device__ unsigned g_scoreEnc[BB * NP];
__device__ float    g_fscore[BB * NP];
__device__ int      g_pidx[BB * KSEL];

// ---------------- helpers ----------------
__device__ __forceinline__ unsigned fenc(float f) {
    unsigned u = __float_as_uint(f);
    return (u & 0x80000000u) ? ~u : (u | 0x80000000u);
}
__device__ __forceinline__ float fdec(unsigned u) {
    return __uint_as_float((u & 0x80000000u) ? (u & 0x7fffffffu) : ~u);
}
__device__ __forceinline__ float gelu_f(float x) {
    return 0.5f * x * (1.0f + erff(x * 0.70710678118654752f));
}
__device__ __forceinline__ ull pack2(float x, float y) {
    ull r; asm("mov.b64 %0, {%1, %2};" : "=l"(r) : "f"(x), "f"(y)); return r;
}
__device__ __forceinline__ float2 unpack2(ull v) {
    float2 r; asm("mov.b64 {%0, %1}, %2;" : "=f"(r.x), "=f"(r.y) : "l"(v)); return r;
}
__device__ __forceinline__ void fma2(ull& c, ull a, ull b) {
    asm("fma.rn.f32x2 %0, %1, %2, %0;" : "+l"(c) : "l"(a), "l"(b));
}
union F4U { float4 f; ull u[2]; };

__device__ __forceinline__ u32 smem_u32(const void* p) {
    u32 a; asm("{ .reg .u64 t; cvta.to.shared.u64 t, %1; cvt.u32.u64 %0, t; }" : "=r"(a) : "l"(p));
    return a;
}

// bf16 residual split: a = h + m + O(2^-18 |a|)
__device__ __forceinline__ void split2(float a, __nv_bfloat16& h, __nv_bfloat16& m) {
    h = __float2bfloat16(a);
    m = __float2bfloat16(a - __bfloat162float(h));
}

// ---------------- mma.sync / ldmatrix / cp.async (baseline PTX, plain sm_103-legal) ----------------
__device__ __forceinline__ void mma16816(float* d, const u32* a, u32 b0, u32 b1) {
    asm volatile("mma.sync.aligned.m16n8k16.row.col.f32.bf16.bf16.f32 "
        "{%0,%1,%2,%3}, {%4,%5,%6,%7}, {%8,%9}, {%0,%1,%2,%3};"
        : "+f"(d[0]), "+f"(d[1]), "+f"(d[2]), "+f"(d[3])
        : "r"(a[0]), "r"(a[1]), "r"(a[2]), "r"(a[3]), "r"(b0), "r"(b1));
}
__device__ __forceinline__ void ldsm4(u32* r, u32 addr) {
    asm volatile("ldmatrix.sync.aligned.m8n8.x4.shared.b16 {%0,%1,%2,%3}, [%4];"
        : "=r"(r[0]), "=r"(r[1]), "=r"(r[2]), "=r"(r[3]) : "r"(addr));
}
__device__ __forceinline__ void cpasync16(u32 dst, const void* src) {
    asm volatile("cp.async.cg.shared.global [%0], [%1], 16;" :: "r"(dst), "l"(src));
}
#define CP_COMMIT() asm volatile("cp.async.commit_group;" ::: "memory")
#define CP_WAIT(n)  asm volatile("cp.async.wait_group %0;" :: "n"(n) : "memory")

// ---------------- GEMM tiling constants ----------------
#define RPAD   80                    // 32 bf16 = 64B data + 16B pad (conflict-free ldmatrix)
#define PLANE  (128 * RPAD)          // 10240 B
#define STGB   (4 * PLANE)           // A(h,m) + B(h,m) per stage = 40960 B
#define GSMEM  (2 * STGB)            // 81920 B, 2-stage

// ---------------- K0: init mask + score buffers ----------------
__global__ void k_init() {
    int t = blockIdx.x * blockDim.x + threadIdx.x;
    if (t < BB * NIN) g_mask[t] = 0.0f;
    if (t < BB * NP)  g_scoreEnc[t] = 0u;
}

__global__ void k_scatter(const int* __restrict__ sidx) {
    int t = blockIdx.x * blockDim.x + threadIdx.x;
    if (t < BB * KIN) {
        int b = t >> 9;
        g_mask[b * NIN + sidx[t]] = 1.0f;
    }
}

// ---------------- split A into 2 bf16 planes ----------------
union B4U { __nv_bfloat16 h[4]; ull u; };

__global__ void k_splitA(const float* __restrict__ act) {
    size_t t = (size_t)blockIdx.x * 256 + threadIdx.x;   // over float4s
    size_t bs = t >> 7;                                  // KIN/4 = 128
    int k4 = (int)(t & 127);
    int b = (int)(bs >> 11), s = (int)(bs & 2047);
    float4 v = ((const float4*)act)[t];
    float vv[4] = { v.x, v.y, v.z, v.w };
    B4U hh, mm;
#pragma unroll
    for (int i = 0; i < 4; i++) split2(vv[i], hh.h[i], mm.h[i]);
    const size_t PL = (size_t)SS * KIN;
    size_t base = ((size_t)(b * 2) * SS + s) * KIN + k4 * 4;
    *(ull*)(g_Asp + base)      = hh.u;
    *(ull*)(g_Asp + base + PL) = mm.u;
}

// ---------------- gather selW rows from cw + split into 2 bf16 planes ----------------
union B2U { __nv_bfloat16 h[2]; u32 u; };

__global__ void k_gatherB(const float* __restrict__ cw, const int* __restrict__ sidx) {
    __shared__ float row[NIN];
    int p = blockIdx.x, tid = threadIdx.x;
    for (int i = tid; i < NIN; i += 256) row[i] = cw[(size_t)p * NIN + i];
    __syncthreads();
    const size_t PL = (size_t)NP * KIN;
#pragma unroll 1
    for (int b = 0; b < BB; b++) {
        int k = tid * 2;
        int i0 = sidx[b * KIN + k], i1 = sidx[b * KIN + k + 1];
        B2U hh, mm;
        split2(row[i0], hh.h[0], mm.h[0]);
        split2(row[i1], hh.h[1], mm.h[1]);
        size_t base = ((size_t)(b * 2) * NP + p) * KIN + k;
        *(u32*)(g_Bsp + base)      = hh.u;
        *(u32*)(g_Bsp + base + PL) = mm.u;
    }
}

// ---------------- K1: score GEMM (HMMA bf16 3-pass) -> per-(b,p) max of z ----------------
__global__ __launch_bounds__(256)
void k_gemm1s() {
    extern __shared__ char smem[];
    const u32 sbase = smem_u32(smem);
    const int tid = threadIdx.x;
    const int wid = tid >> 5, lid = tid & 31;
    const int wm = wid & 3, wn = wid >> 2;       // warp tile 32 x 64
    const int b  = blockIdx.z;
    const int p0 = blockIdx.x * 128;
    const int s0 = blockIdx.y * 128;

    float acc[2][8][4];
#pragma unroll
    for (int i = 0; i < 2; i++)
#pragma unroll
        for (int j = 0; j < 8; j++)
#pragma unroll
            for (int r = 0; r < 4; r++) acc[i][j][r] = 0.0f;

    auto load_stage = [&](int ks, int buf) {
        const int k0 = ks * 32;
        u32 sg = sbase + buf * STGB;
#pragma unroll
        for (int i = 0; i < 4; i++) {   // A: 1024 chunks
            int idx = tid + i * 256;
            int sp = idx >> 9, rem = idx & 511;
            int r = rem >> 2, c = rem & 3;
            const __nv_bfloat16* g = g_Asp + ((size_t)(b * 2 + sp) * SS + s0 + r) * KIN + k0 + c * 8;
            cpasync16(sg + sp * PLANE + r * RPAD + c * 16, g);
        }
#pragma unroll
        for (int i = 0; i < 4; i++) {   // B: 1024 chunks
            int idx = tid + i * 256;
            int sp = idx >> 9, rem = idx & 511;
            int r = rem >> 2, c = rem & 3;
            const __nv_bfloat16* g = g_Bsp + ((size_t)(b * 2 + sp) * NP + p0 + r) * KIN + k0 + c * 8;
            cpasync16(sg + 2 * PLANE + sp * PLANE + r * RPAD + c * 16, g);
        }
    };

    const u32 aoff = (u32)((wm * 32 + (lid & 15)) * RPAD + (lid >> 4) * 16);
    const u32 boff = (u32)((wn * 64 + (lid & 15)) * RPAD + (lid >> 4) * 16);

    load_stage(0, 0); CP_COMMIT();

#pragma unroll 1
    for (int ks = 0; ks < KIN / 32; ks++) {
        int buf = ks & 1;
        if (ks < KIN / 32 - 1) { load_stage(ks + 1, buf ^ 1); CP_COMMIT(); CP_WAIT(1); }
        else                   { CP_WAIT(0); }
        __syncthreads();
        u32 sA = sbase + buf * STGB;
        u32 sB = sA + 2 * PLANE;
#pragma unroll
        for (int kk = 0; kk < 2; kk++) {
            u32 ah[2][4], am[2][4];
#pragma unroll
            for (int mt = 0; mt < 2; mt++) {
                ldsm4(ah[mt], sA + aoff + mt * (16 * RPAD) + kk * 32);
                ldsm4(am[mt], sA + PLANE + aoff + mt * (16 * RPAD) + kk * 32);
            }
            u32 bh[4][4], bm[4][4];
#pragma unroll
            for (int nt2 = 0; nt2 < 4; nt2++) {
                ldsm4(bh[nt2], sB + boff + nt2 * (16 * RPAD) + kk * 32);
                ldsm4(bm[nt2], sB + PLANE + boff + nt2 * (16 * RPAD) + kk * 32);
            }
#pragma unroll
            for (int mt = 0; mt < 2; mt++)
#pragma unroll
                for (int nt2 = 0; nt2 < 4; nt2++) {
                    mma16816(acc[mt][2 * nt2],     ah[mt], bh[nt2][0], bh[nt2][2]);
                    mma16816(acc[mt][2 * nt2 + 1], ah[mt], bh[nt2][1], bh[nt2][3]);
                    mma16816(acc[mt][2 * nt2],     ah[mt], bm[nt2][0], bm[nt2][2]);
                    mma16816(acc[mt][2 * nt2 + 1], ah[mt], bm[nt2][1], bm[nt2][3]);
                    mma16816(acc[mt][2 * nt2],     am[mt], bh[nt2][0], bh[nt2][2]);
                    mma16816(acc[mt][2 * nt2 + 1], am[mt], bh[nt2][1], bh[nt2][3]);
                }
        }
        __syncthreads();
    }

    // ---- epilogue: per-column max over 128 s-rows (gelu deferred to k_rel; monotone on x>0)
    u32* scol = (u32*)smem;
    if (tid < 128) scol[tid] = 0u;
    __syncthreads();
#pragma unroll
    for (int nt = 0; nt < 8; nt++) {
        float m0 = fmaxf(fmaxf(acc[0][nt][0], acc[0][nt][2]), fmaxf(acc[1][nt][0], acc[1][nt][2]));
        float m1 = fmaxf(fmaxf(acc[0][nt][1], acc[0][nt][3]), fmaxf(acc[1][nt][1], acc[1][nt][3]));
#pragma unroll
        for (int mk = 4; mk < 32; mk <<= 1) {
            m0 = fmaxf(m0, __shfl_xor_sync(0xffffffffu, m0, mk));
            m1 = fmaxf(m1, __shfl_xor_sync(0xffffffffu, m1, mk));
        }
        if (lid < 4) {
            atomicMax(&scol[wn * 64 + nt * 8 + 2 * lid],     fenc(m0));
            atomicMax(&scol[wn * 64 + nt * 8 + 2 * lid + 1], fenc(m1));
        }
    }
    __syncthreads();
    if (tid < 128) atomicMax(&g_scoreEnc[b * NP + p0 + tid], scol[tid]);
}

// ---------------- K2: hidden MLP ----------------
__global__ void k_hidden(const float* __restrict__ w1, const float* __restrict__ b1) {
    int j = blockIdx.x;
    int tid = threadIdx.x;
    const float* wr = w1 + (size_t)j * NIN;
    float acc[BB];
#pragma unroll
    for (int b = 0; b < BB; b++) acc[b] = 0.0f;
    for (int n = tid; n < NIN; n += 256) {
        float w = wr[n];
#pragma unroll
        for (int b = 0; b < BB; b++) acc[b] += w * g_mask[b * NIN + n];
    }
    __shared__ float red[BB][256];
#pragma unroll
    for (int b = 0; b < BB; b++) red[b][tid] = acc[b];
    __syncthreads();
    for (int s1 = 128; s1 > 0; s1 >>= 1) {
        if (tid < s1) {
#pragma unroll
            for (int b = 0; b < BB; b++) red[b][tid] += red[b][tid + s1];
        }
        __syncthreads();
    }
    if (tid < BB) g_h[tid * HID + j] = gelu_f(red[tid][0] + b1[j]);
}

// ---------------- K3: relevance + final scores (gelu applied to max-z here) ----------------
__global__ void k_rel(const float* __restrict__ w2, const float* __restrict__ b2) {
    int warp = threadIdx.x >> 5, lane = threadIdx.x & 31;
    int p = blockIdx.x * 8 + warp;
    const float* wr = w2 + (size_t)p * HID;
    float acc[BB];
#pragma unroll
    for (int b = 0; b < BB; b++) acc[b] = 0.0f;
    for (int j = lane; j < HID; j += 32) {
        float w = wr[j];
#pragma unroll
        for (int b = 0; b < BB; b++) acc[b] += w * g_h[b * HID + j];
    }
#pragma unroll
    for (int o = 16; o > 0; o >>= 1)
#pragma unroll
        for (int b = 0; b < BB; b++) acc[b] += __shfl_down_sync(0xffffffffu, acc[b], o);
    if (lane == 0) {
#pragma unroll
        for (int b = 0; b < BB; b++) {
            float rel = acc[b] + b2[p];
            float sig = 1.0f / (1.0f + expf(-rel));
            g_fscore[b * NP + p] = gelu_f(fdec(g_scoreEnc[b * NP + p])) * sig;
        }
    }
}

// ---------------- K4: per-batch top-256 via bitonic sort ----------------
__global__ void k_topk() {
    __shared__ ull key[NP];
    int b = blockIdx.x, tid = threadIdx.x;
    for (int i = tid; i < NP; i += 512)
        key[i] = ((ull)fenc(g_fscore[b * NP + i]) << 32) | (unsigned)i;
    __syncthreads();
    for (int k = 2; k <= NP; k <<= 1) {
        for (int j = k >> 1; j > 0; j >>= 1) {
            for (int i = tid; i < NP; i += 512) {
                int ix = i ^ j;
                if (ix > i) {
                    ull x = key[i], y = key[ix];
                    bool desc = ((i & k) == 0);
                    if (desc ? (x < y) : (x > y)) { key[i] = y; key[ix] = x; }
                }
            }
            __syncthreads();
        }
    }
    if (tid < KSEL) g_pidx[b * KSEL + tid] = (int)(key[tid] & 0xffffffffu);
}

// ---------------- K5: recompute selected columns: pasel = gelu(A @ Bsel) ----------------
__global__ __launch_bounds__(256)
void k_pasel() {
    extern __shared__ char smem[];
    __shared__ int pidx_s[128];
    const u32 sbase = smem_u32(smem);
    const int tid = threadIdx.x;
    const int wid = tid >> 5, lid = tid & 31;
    const int wm = wid & 3, wn = wid >> 2;
    const int b  = blockIdx.z;
    const int n0 = blockIdx.x * 128;
    const int s0 = blockIdx.y * 128;

    if (tid < 128) pidx_s[tid] = g_pidx[b * KSEL + n0 + tid];
    __syncthreads();

    float acc[2][8][4];
#pragma unroll
    for (int i = 0; i < 2; i++)
#pragma unroll
        for (int j = 0; j < 8; j++)
#pragma unroll
            for (int r = 0; r < 4; r++) acc[i][j][r] = 0.0f;

    auto load_stage = [&](int ks, int buf) {
        const int k0 = ks * 32;
        u32 sg = sbase + buf * STGB;
#pragma unroll
        for (int i = 0; i < 4; i++) {
            int idx = tid + i * 256;
            int sp = idx >> 9, rem = idx & 511;
            int r = rem >> 2, c = rem & 3;
            const __nv_bfloat16* g = g_Asp + ((size_t)(b * 2 + sp) * SS + s0 + r) * KIN + k0 + c * 8;
            cpasync16(sg + sp * PLANE + r * RPAD + c * 16, g);
        }
#pragma unroll
        for (int i = 0; i < 4; i++) {
            int idx = tid + i * 256;
            int sp = idx >> 9, rem = idx & 511;
            int r = rem >> 2, c = rem & 3;
            int p = pidx_s[r];
            const __nv_bfloat16* g = g_Bsp + ((size_t)(b * 2 + sp) * NP + p) * KIN + k0 + c * 8;
            cpasync16(sg + 2 * PLANE + sp * PLANE + r * RPAD + c * 16, g);
        }
    };

    const u32 aoff = (u32)((wm * 32 + (lid & 15)) * RPAD + (lid >> 4) * 16);
    const u32 boff = (u32)((wn * 64 + (lid & 15)) * RPAD + (lid >> 4) * 16);

    load_stage(0, 0); CP_COMMIT();

#pragma unroll 1
    for (int ks = 0; ks < KIN / 32; ks++) {
        int buf = ks & 1;
        if (ks < KIN / 32 - 1) { load_stage(ks + 1, buf ^ 1); CP_COMMIT(); CP_WAIT(1); }
        else                   { CP_WAIT(0); }
        __syncthreads();
        u32 sA = sbase + buf * STGB;
        u32 sB = sA + 2 * PLANE;
#pragma unroll
        for (int kk = 0; kk < 2; kk++) {
            u32 ah[2][4], am[2][4];
#pragma unroll
            for (int mt = 0; mt < 2; mt++) {
                ldsm4(ah[mt], sA + aoff + mt * (16 * RPAD) + kk * 32);
                ldsm4(am[mt], sA + PLANE + aoff + mt * (16 * RPAD) + kk * 32);
            }
            u32 bh[4][4], bm[4][4];
#pragma unroll
            for (int nt2 = 0; nt2 < 4; nt2++) {
                ldsm4(bh[nt2], sB + boff + nt2 * (16 * RPAD) + kk * 32);
                ldsm4(bm[nt2], sB + PLANE + boff + nt2 * (16 * RPAD) + kk * 32);
            }
#pragma unroll
            for (int mt = 0; mt < 2; mt++)
#pragma unroll
                for (int nt2 = 0; nt2 < 4; nt2++) {
                    mma16816(acc[mt][2 * nt2],     ah[mt], bh[nt2][0], bh[nt2][2]);
                    mma16816(acc[mt][2 * nt2 + 1], ah[mt], bh[nt2][1], bh[nt2][3]);
                    mma16816(acc[mt][2 * nt2],     ah[mt], bm[nt2][0], bm[nt2][2]);
                    mma16816(acc[mt][2 * nt2 + 1], ah[mt], bm[nt2][1], bm[nt2][3]);
                    mma16816(acc[mt][2 * nt2],     am[mt], bh[nt2][0], bh[nt2][2]);
                    mma16816(acc[mt][2 * nt2 + 1], am[mt], bh[nt2][1], bh[nt2][3]);
                }
        }
        __syncthreads();
    }

    // epilogue: gelu + store to g_pasel [b][s][j]
#pragma unroll
    for (int mt = 0; mt < 2; mt++)
#pragma unroll
        for (int nt = 0; nt < 8; nt++) {
            int row = s0 + wm * 32 + mt * 16 + (lid >> 2);
            int col = n0 + wn * 64 + nt * 8 + 2 * (lid & 3);
            float* po = g_pasel + ((size_t)b * SS + row) * KSEL + col;
            *(float2*)po = make_float2(gelu_f(acc[mt][nt][0]), gelu_f(acc[mt][nt][1]));
            *(float2*)(po + 8 * KSEL) = make_float2(gelu_f(acc[mt][nt][2]), gelu_f(acc[mt][nt][3]));
        }
}

// ---------------- K6: final GEMM (FFMA2): out = pasel @ proj[pidx] ----------------
__global__ __launch_bounds__(256, 2)
void k_gemm3(const float* __restrict__ proj, float* __restrict__ out) {
    const int b  = blockIdx.z;
    const int d0 = blockIdx.x * 128;
    const int s0 = blockIdx.y * 128;
    const float* Ab   = g_pasel + (size_t)b * SS * KSEL;
    const int*   idxb = g_pidx  + b * KSEL;

    __shared__ float As[16][132];
    __shared__ float Bs[16][128];

    const int tid = threadIdx.x;
    const int tm = tid >> 4, tn = tid & 15;

    ull acc[8][4];
#pragma unroll
    for (int r = 0; r < 8; r++)
#pragma unroll
        for (int c = 0; c < 4; c++) acc[r][c] = 0ULL;

    for (int k0 = 0; k0 < KSEL; k0 += 16) {
#pragma unroll
        for (int q = 0; q < 2; q++) {
            int f = tid + q * 256;
            int row = f >> 2, c4 = f & 3;
            float4 v = *(const float4*)(Ab + (size_t)(s0 + row) * KSEL + k0 + c4 * 4);
            As[c4 * 4 + 0][row] = v.x; As[c4 * 4 + 1][row] = v.y;
            As[c4 * 4 + 2][row] = v.z; As[c4 * 4 + 3][row] = v.w;
        }
#pragma unroll
        for (int q = 0; q < 2; q++) {
            int f = tid + q * 256;
            int kk = f >> 5, c4 = f & 31;
            int n = idxb[k0 + kk];
            *(float4*)&Bs[kk][c4 * 4] =
                *(const float4*)(proj + (size_t)n * DM + d0 + c4 * 4);
        }
        __syncthreads();
#pragma unroll
        for (int kk = 0; kk < 16; ++kk) {
            F4U a0, a1, b0, b1;
            a0.f = *(const float4*)&As[kk][tm * 8];
            a1.f = *(const float4*)&As[kk][tm * 8 + 4];
            b0.f = *(const float4*)&Bs[kk][tn * 8];
            b1.f = *(const float4*)&Bs[kk][tn * 8 + 4];
            ull bb[4] = { b0.u[0], b0.u[1], b1.u[0], b1.u[1] };
            ull aa[8];
            aa[0] = pack2(a0.f.x, a0.f.x); aa[1] = pack2(a0.f.y, a0.f.y);
            aa[2] = pack2(a0.f.z, a0.f.z); aa[3] = pack2(a0.f.w, a0.f.w);
            aa[4] = pack2(a1.f.x, a1.f.x); aa[5] = pack2(a1.f.y, a1.f.y);
            aa[6] = pack2(a1.f.z, a1.f.z); aa[7] = pack2(a1.f.w, a1.f.w);
#pragma unroll
            for (int r = 0; r < 8; r++)
#pragma unroll
                for (int c = 0; c < 4; c++) fma2(acc[r][c], aa[r], bb[c]);
        }
        __syncthreads();
    }
#pragma unroll
    for (int r = 0; r < 8; r++) {
        int s = s0 + tm * 8 + r;
        float* po = out + ((size_t)b * SS + s) * DM + d0 + tn * 8;
        float2 v0 = unpack2(acc[r][0]), v1 = unpack2(acc[r][1]);
        float2 v2 = unpack2(acc[r][2]), v3 = unpack2(acc[r][3]);
        *(float4*)po       = make_float4(v0.x, v0.y, v1.x, v1.y);
        *(float4*)(po + 4) = make_float4(v2.x, v2.y, v3.x, v3.y);
    }
}

// ---------------- entry ----------------
extern "C" void kernel_launch(void* const* d_in, const int* in_sizes, int n_in,
                              void* d_out, int out_size) {
    const float* act  = (const float*)d_in[0];
    const int*   sidx = (const int*)d_in[1];
    int o = (n_in >= 9 && in_sizes[2] == 1) ? 3 : 2;
    const float* cw   = (const float*)d_in[o + 0];
    const float* proj = (const float*)d_in[o + 1];
    const float* w1   = (const float*)d_in[o + 2];
    const float* b1   = (const float*)d_in[o + 3];
    const float* w2   = (const float*)d_in[o + 4];
    const float* b2   = (const float*)d_in[o + 5];
    float* out = (float*)d_out;

    k_init<<<(BB * NP + 255) / 256, 256>>>();
    k_scatter<<<(BB * KIN + 255) / 256, 256>>>(sidx);
    k_splitA<<<(BB * SS * KIN / 4) / 256, 256>>>(act);
    k_gatherB<<<NP, 256>>>(cw, sidx);

    cudaFuncSetAttribute(k_gemm1s, cudaFuncAttributeMaxDynamicSharedMemorySize, GSMEM);
    k_gemm1s<<<dim3(NP / 128, SS / 128, BB), 256, GSMEM>>>();

    k_hidden<<<HID, 256>>>(w1, b1);
    k_rel<<<NP / 8, 256>>>(w2, b2);
    k_topk<<<BB, 512>>>();

    cudaFuncSetAttribute(k_pasel, cudaFuncAttributeMaxDynamicSharedMemorySize, GSMEM);
    k_pasel<<<dim3(KSEL / 128, SS / 128, BB), 256, GSMEM>>>();

    k_gemm3<<<dim3(DM / 128, SS / 128, BB), 256>>>(proj, out);
}

// round 4
// speedup vs baseline: 2.7084x; 1.5272x over previous
#include <cuda_runtime.h>
#include <cuda_bf16.h>

#define BB   8
#define SS   2048
#define KIN  512
#define NIN  2048
#define NP   4096
#define HID  4096
#define DM   1024
#define KSEL 256
#define NC   512    // refine candidate count

typedef unsigned long long ull;
typedef unsigned int u32;

// ---------------- scratch ----------------
__device__ __align__(256) __nv_bfloat16 g_Asp[(size_t)BB * 2 * SS * KIN];   // A splits (h,m)
__device__ __align__(256) __nv_bfloat16 g_Bh [(size_t)BB * NP * KIN];       // B h-plane full
__device__ __align__(256) __nv_bfloat16 g_Bc [(size_t)BB * 2 * NC * KIN];   // B splits, 512 cands
__device__ __align__(256) __nv_bfloat16 g_PC [(size_t)BB * 2 * SS * NC];    // gelu(z) splits, 512 cands
__device__ __align__(256) __nv_bfloat16 g_PA [(size_t)BB * 2 * SS * KSEL];  // compacted 256
__device__ __align__(256) __nv_bfloat16 g_Pr [(size_t)BB * 2 * DM * KSEL];  // proj^T splits
__device__ float    g_mask[BB * NIN];
__device__ float    g_h[BB * HID];
__device__ float    g_sig[BB * NP];
__device__ unsigned g_scoreEnc[BB * NP];     // approx max-z (encoded)
__device__ unsigned g_scoreEnc2[BB * NC];    // exact max-z per candidate slot
__device__ float    g_fscore[BB * NP];       // approx final scores
__device__ int      g_pidx512[BB * NC];      // candidate global process ids
__device__ int      g_pidx[BB * KSEL];       // final selected global ids
__device__ int      g_cmap[BB * KSEL];       // final selected -> slot in 512 list

// ---------------- helpers ----------------
__device__ __forceinline__ unsigned fenc(float f) {
    unsigned u = __float_as_uint(f);
    return (u & 0x80000000u) ? ~u : (u | 0x80000000u);
}
__device__ __forceinline__ float fdec(unsigned u) {
    return __uint_as_float((u & 0x80000000u) ? (u & 0x7fffffffu) : ~u);
}
__device__ __forceinline__ float gelu_f(float x) {
    return 0.5f * x * (1.0f + erff(x * 0.70710678118654752f));
}
__device__ __forceinline__ u32 smem_u32(const void* p) {
    u32 a; asm("{ .reg .u64 t; cvta.to.shared.u64 t, %1; cvt.u32.u64 %0, t; }" : "=r"(a) : "l"(p));
    return a;
}
__device__ __forceinline__ void split2(float a, __nv_bfloat16& h, __nv_bfloat16& m) {
    h = __float2bfloat16(a);
    m = __float2bfloat16(a - __bfloat162float(h));
}
__device__ __forceinline__ u32 packbf2(float a, float b) {
    __nv_bfloat162 t = __floats2bfloat162_rn(a, b);  // not used; keep explicit path below
    return *(u32*)&t;
}

// ---------------- mma.sync / ldmatrix / cp.async ----------------
__device__ __forceinline__ void mma16816(float* d, const u32* a, u32 b0, u32 b1) {
    asm volatile("mma.sync.aligned.m16n8k16.row.col.f32.bf16.bf16.f32 "
        "{%0,%1,%2,%3}, {%4,%5,%6,%7}, {%8,%9}, {%0,%1,%2,%3};"
        : "+f"(d[0]), "+f"(d[1]), "+f"(d[2]), "+f"(d[3])
        : "r"(a[0]), "r"(a[1]), "r"(a[2]), "r"(a[3]), "r"(b0), "r"(b1));
}
__device__ __forceinline__ void ldsm4(u32* r, u32 addr) {
    asm volatile("ldmatrix.sync.aligned.m8n8.x4.shared.b16 {%0,%1,%2,%3}, [%4];"
        : "=r"(r[0]), "=r"(r[1]), "=r"(r[2]), "=r"(r[3]) : "r"(addr));
}
__device__ __forceinline__ void cpasync16(u32 dst, const void* src) {
    asm volatile("cp.async.cg.shared.global [%0], [%1], 16;" :: "r"(dst), "l"(src));
}
#define CP_COMMIT() asm volatile("cp.async.commit_group;" ::: "memory")
#define CP_WAIT(n)  asm volatile("cp.async.wait_group %0;" :: "n"(n) : "memory")

#define RPAD   80
#define PLANE  (128 * RPAD)
#define STGB2  (2 * PLANE)          // 1-plane A + 1-plane B stage
#define STGB4  (4 * PLANE)          // 2-plane A + 2-plane B stage
#define GSMEM2 (2 * STGB2)          // 40960
#define GSMEM4 (2 * STGB4)          // 81920

// ---------------- K0 ----------------
__global__ void k_init() {
    int t = blockIdx.x * blockDim.x + threadIdx.x;
    if (t < BB * NIN) g_mask[t] = 0.0f;
    if (t < BB * NP)  g_scoreEnc[t] = 0u;
    if (t < BB * NC)  g_scoreEnc2[t] = 0u;
}

__global__ void k_scatter(const int* __restrict__ sidx) {
    int t = blockIdx.x * blockDim.x + threadIdx.x;
    if (t < BB * KIN) {
        int b = t >> 9;
        g_mask[b * NIN + sidx[t]] = 1.0f;
    }
}

// ---------------- split A into 2 bf16 planes ----------------
union B4U { __nv_bfloat16 h[4]; ull u; };
union B2U { __nv_bfloat16 h[2]; u32 u; };

__global__ void k_splitA(const float* __restrict__ act) {
    size_t t = (size_t)blockIdx.x * 256 + threadIdx.x;
    size_t bs = t >> 7;
    int k4 = (int)(t & 127);
    int b = (int)(bs >> 11), s = (int)(bs & 2047);
    float4 v = ((const float4*)act)[t];
    float vv[4] = { v.x, v.y, v.z, v.w };
    B4U hh, mm;
#pragma unroll
    for (int i = 0; i < 4; i++) split2(vv[i], hh.h[i], mm.h[i]);
    const size_t PL = (size_t)SS * KIN;
    size_t base = ((size_t)(b * 2) * SS + s) * KIN + k4 * 4;
    *(ull*)(g_Asp + base)      = hh.u;
    *(ull*)(g_Asp + base + PL) = mm.u;
}

// ---------------- gather B h-plane (full 4096 rows) ----------------
__global__ void k_gatherBh(const float* __restrict__ cw, const int* __restrict__ sidx) {
    __shared__ float row[NIN];
    int p = blockIdx.x, tid = threadIdx.x;
    for (int i = tid; i < NIN; i += 256) row[i] = cw[(size_t)p * NIN + i];
    __syncthreads();
#pragma unroll 1
    for (int b = 0; b < BB; b++) {
        int k = tid * 2;
        int i0 = sidx[b * KIN + k], i1 = sidx[b * KIN + k + 1];
        B2U hh;
        hh.h[0] = __float2bfloat16(row[i0]);
        hh.h[1] = __float2bfloat16(row[i1]);
        *(u32*)(g_Bh + ((size_t)b * NP + p) * KIN + k) = hh.u;
    }
}

// ---------------- gather B splits for 512 candidates ----------------
__global__ void k_gatherB512(const float* __restrict__ cw, const int* __restrict__ sidx) {
    __shared__ float row[NIN];
    int blk = blockIdx.x;                 // b*NC + j
    int b = blk >> 9, j = blk & (NC - 1);
    int tid = threadIdx.x;
    int p = g_pidx512[b * NC + j];
    for (int i = tid; i < NIN; i += 256) row[i] = cw[(size_t)p * NIN + i];
    __syncthreads();
    int k = tid * 2;
    int i0 = sidx[b * KIN + k], i1 = sidx[b * KIN + k + 1];
    B2U hh, mm;
    split2(row[i0], hh.h[0], mm.h[0]);
    split2(row[i1], hh.h[1], mm.h[1]);
    const size_t PL = (size_t)NC * KIN;
    size_t base = ((size_t)(b * 2) * NC + j) * KIN + k;
    *(u32*)(g_Bc + base)      = hh.u;
    *(u32*)(g_Bc + base + PL) = mm.u;
}

// ---------------- K1a: approx score GEMM (single-pass bf16) -> max-z ----------------
__global__ __launch_bounds__(256)
void k_gemm1a() {
    extern __shared__ char smem[];
    const u32 sbase = smem_u32(smem);
    const int tid = threadIdx.x;
    const int wid = tid >> 5, lid = tid & 31;
    const int wm = wid & 3, wn = wid >> 2;
    const int b  = blockIdx.z;
    const int p0 = blockIdx.x * 128;
    const int s0 = blockIdx.y * 128;

    float acc[2][8][4];
#pragma unroll
    for (int i = 0; i < 2; i++)
#pragma unroll
        for (int j = 0; j < 8; j++)
#pragma unroll
            for (int r = 0; r < 4; r++) acc[i][j][r] = 0.0f;

    auto load_stage = [&](int ks, int buf) {
        const int k0 = ks * 32;
        u32 sg = sbase + buf * STGB2;
#pragma unroll
        for (int i = 0; i < 2; i++) {   // A h-plane: 512 chunks
            int idx = tid + i * 256;
            int r = idx >> 2, c = idx & 3;
            const __nv_bfloat16* g = g_Asp + ((size_t)(b * 2) * SS + s0 + r) * KIN + k0 + c * 8;
            cpasync16(sg + r * RPAD + c * 16, g);
        }
#pragma unroll
        for (int i = 0; i < 2; i++) {   // B h-plane
            int idx = tid + i * 256;
            int r = idx >> 2, c = idx & 3;
            const __nv_bfloat16* g = g_Bh + ((size_t)b * NP + p0 + r) * KIN + k0 + c * 8;
            cpasync16(sg + PLANE + r * RPAD + c * 16, g);
        }
    };

    const u32 aoff = (u32)((wm * 32 + (lid & 15)) * RPAD + (lid >> 4) * 16);
    const u32 boff = (u32)((wn * 64 + (lid & 15)) * RPAD + (lid >> 4) * 16);

    load_stage(0, 0); CP_COMMIT();

#pragma unroll 1
    for (int ks = 0; ks < KIN / 32; ks++) {
        int buf = ks & 1;
        if (ks < KIN / 32 - 1) { load_stage(ks + 1, buf ^ 1); CP_COMMIT(); CP_WAIT(1); }
        else                   { CP_WAIT(0); }
        __syncthreads();
        u32 sA = sbase + buf * STGB2;
        u32 sB = sA + PLANE;
#pragma unroll
        for (int kk = 0; kk < 2; kk++) {
            u32 ah[2][4];
#pragma unroll
            for (int mt = 0; mt < 2; mt++)
                ldsm4(ah[mt], sA + aoff + mt * (16 * RPAD) + kk * 32);
            u32 bh[4][4];
#pragma unroll
            for (int nt2 = 0; nt2 < 4; nt2++)
                ldsm4(bh[nt2], sB + boff + nt2 * (16 * RPAD) + kk * 32);
#pragma unroll
            for (int mt = 0; mt < 2; mt++)
#pragma unroll
                for (int nt2 = 0; nt2 < 4; nt2++) {
                    mma16816(acc[mt][2 * nt2],     ah[mt], bh[nt2][0], bh[nt2][2]);
                    mma16816(acc[mt][2 * nt2 + 1], ah[mt], bh[nt2][1], bh[nt2][3]);
                }
        }
        __syncthreads();
    }

    // per-column max of z
    u32* scol = (u32*)smem;
    if (tid < 128) scol[tid] = 0u;
    __syncthreads();
#pragma unroll
    for (int nt = 0; nt < 8; nt++) {
        float m0 = fmaxf(fmaxf(acc[0][nt][0], acc[0][nt][2]), fmaxf(acc[1][nt][0], acc[1][nt][2]));
        float m1 = fmaxf(fmaxf(acc[0][nt][1], acc[0][nt][3]), fmaxf(acc[1][nt][1], acc[1][nt][3]));
#pragma unroll
        for (int mk = 4; mk < 32; mk <<= 1) {
            m0 = fmaxf(m0, __shfl_xor_sync(0xffffffffu, m0, mk));
            m1 = fmaxf(m1, __shfl_xor_sync(0xffffffffu, m1, mk));
        }
        if (lid < 4) {
            atomicMax(&scol[wn * 64 + nt * 8 + 2 * lid],     fenc(m0));
            atomicMax(&scol[wn * 64 + nt * 8 + 2 * lid + 1], fenc(m1));
        }
    }
    __syncthreads();
    if (tid < 128) atomicMax(&g_scoreEnc[b * NP + p0 + tid], scol[tid]);
}

// ---------------- K2: hidden MLP ----------------
__global__ void k_hidden(const float* __restrict__ w1, const float* __restrict__ b1) {
    int j = blockIdx.x;
    int tid = threadIdx.x;
    const float* wr = w1 + (size_t)j * NIN;
    float acc[BB];
#pragma unroll
    for (int b = 0; b < BB; b++) acc[b] = 0.0f;
    for (int n = tid; n < NIN; n += 256) {
        float w = wr[n];
#pragma unroll
        for (int b = 0; b < BB; b++) acc[b] += w * g_mask[b * NIN + n];
    }
    __shared__ float red[BB][256];
#pragma unroll
    for (int b = 0; b < BB; b++) red[b][tid] = acc[b];
    __syncthreads();
    for (int s1 = 128; s1 > 0; s1 >>= 1) {
        if (tid < s1) {
#pragma unroll
            for (int b = 0; b < BB; b++) red[b][tid] += red[b][tid + s1];
        }
        __syncthreads();
    }
    if (tid < BB) g_h[tid * HID + j] = gelu_f(red[tid][0] + b1[j]);
}

// ---------------- K3: relevance -> sigmoid + approx scores ----------------
__global__ void k_rel(const float* __restrict__ w2, const float* __restrict__ b2) {
    int warp = threadIdx.x >> 5, lane = threadIdx.x & 31;
    int p = blockIdx.x * 8 + warp;
    const float* wr = w2 + (size_t)p * HID;
    float acc[BB];
#pragma unroll
    for (int b = 0; b < BB; b++) acc[b] = 0.0f;
    for (int j = lane; j < HID; j += 32) {
        float w = wr[j];
#pragma unroll
        for (int b = 0; b < BB; b++) acc[b] += w * g_h[b * HID + j];
    }
#pragma unroll
    for (int o = 16; o > 0; o >>= 1)
#pragma unroll
        for (int b = 0; b < BB; b++) acc[b] += __shfl_down_sync(0xffffffffu, acc[b], o);
    if (lane == 0) {
#pragma unroll
        for (int b = 0; b < BB; b++) {
            float rel = acc[b] + b2[p];
            float sig = 1.0f / (1.0f + expf(-rel));
            g_sig[b * NP + p] = sig;
            g_fscore[b * NP + p] = gelu_f(fdec(g_scoreEnc[b * NP + p])) * sig;
        }
    }
}

// ---------------- K4: approx top-512 via bitonic sort ----------------
__global__ void k_topk512() {
    __shared__ ull key[NP];
    int b = blockIdx.x, tid = threadIdx.x;
    for (int i = tid; i < NP; i += 512)
        key[i] = ((ull)fenc(g_fscore[b * NP + i]) << 32) | (unsigned)i;
    __syncthreads();
    for (int k = 2; k <= NP; k <<= 1) {
        for (int j = k >> 1; j > 0; j >>= 1) {
            for (int i = tid; i < NP; i += 512) {
                int ix = i ^ j;
                if (ix > i) {
                    ull x = key[i], y = key[ix];
                    bool desc = ((i & k) == 0);
                    if (desc ? (x < y) : (x > y)) { key[i] = y; key[ix] = x; }
                }
            }
            __syncthreads();
        }
    }
    if (tid < NC) g_pidx512[b * NC + tid] = (int)(key[tid] & 0xffffffffu);
}

// ---------------- K5: refine — exact 3-pass z for 512 cands; store gelu splits + max-z ----------------
__global__ __launch_bounds__(256)
void k_refine() {
    extern __shared__ char smem[];
    const u32 sbase = smem_u32(smem);
    const int tid = threadIdx.x;
    const int wid = tid >> 5, lid = tid & 31;
    const int wm = wid & 3, wn = wid >> 2;
    const int b  = blockIdx.z;
    const int n0 = blockIdx.x * 128;
    const int s0 = blockIdx.y * 128;

    float acc[2][8][4];
#pragma unroll
    for (int i = 0; i < 2; i++)
#pragma unroll
        for (int j = 0; j < 8; j++)
#pragma unroll
            for (int r = 0; r < 4; r++) acc[i][j][r] = 0.0f;

    auto load_stage = [&](int ks, int buf) {
        const int k0 = ks * 32;
        u32 sg = sbase + buf * STGB4;
#pragma unroll
        for (int i = 0; i < 4; i++) {   // A: 2 planes
            int idx = tid + i * 256;
            int sp = idx >> 9, rem = idx & 511;
            int r = rem >> 2, c = rem & 3;
            const __nv_bfloat16* g = g_Asp + ((size_t)(b * 2 + sp) * SS + s0 + r) * KIN + k0 + c * 8;
            cpasync16(sg + sp * PLANE + r * RPAD + c * 16, g);
        }
#pragma unroll
        for (int i = 0; i < 4; i++) {   // B: 2 planes (compact candidates)
            int idx = tid + i * 256;
            int sp = idx >> 9, rem = idx & 511;
            int r = rem >> 2, c = rem & 3;
            const __nv_bfloat16* g = g_Bc + ((size_t)(b * 2 + sp) * NC + n0 + r) * KIN + k0 + c * 8;
            cpasync16(sg + 2 * PLANE + sp * PLANE + r * RPAD + c * 16, g);
        }
    };

    const u32 aoff = (u32)((wm * 32 + (lid & 15)) * RPAD + (lid >> 4) * 16);
    const u32 boff = (u32)((wn * 64 + (lid & 15)) * RPAD + (lid >> 4) * 16);

    load_stage(0, 0); CP_COMMIT();

#pragma unroll 1
    for (int ks = 0; ks < KIN / 32; ks++) {
        int buf = ks & 1;
        if (ks < KIN / 32 - 1) { load_stage(ks + 1, buf ^ 1); CP_COMMIT(); CP_WAIT(1); }
        else                   { CP_WAIT(0); }
        __syncthreads();
        u32 sA = sbase + buf * STGB4;
        u32 sB = sA + 2 * PLANE;
#pragma unroll
        for (int kk = 0; kk < 2; kk++) {
            u32 ah[2][4], am[2][4];
#pragma unroll
            for (int mt = 0; mt < 2; mt++) {
                ldsm4(ah[mt], sA + aoff + mt * (16 * RPAD) + kk * 32);
                ldsm4(am[mt], sA + PLANE + aoff + mt * (16 * RPAD) + kk * 32);
            }
            u32 bh[4][4], bm[4][4];
#pragma unroll
            for (int nt2 = 0; nt2 < 4; nt2++) {
                ldsm4(bh[nt2], sB + boff + nt2 * (16 * RPAD) + kk * 32);
                ldsm4(bm[nt2], sB + PLANE + boff + nt2 * (16 * RPAD) + kk * 32);
            }
#pragma unroll
            for (int mt = 0; mt < 2; mt++)
#pragma unroll
                for (int nt2 = 0; nt2 < 4; nt2++) {
                    mma16816(acc[mt][2 * nt2],     ah[mt], bh[nt2][0], bh[nt2][2]);
                    mma16816(acc[mt][2 * nt2 + 1], ah[mt], bh[nt2][1], bh[nt2][3]);
                    mma16816(acc[mt][2 * nt2],     ah[mt], bm[nt2][0], bm[nt2][2]);
                    mma16816(acc[mt][2 * nt2 + 1], ah[mt], bm[nt2][1], bm[nt2][3]);
                    mma16816(acc[mt][2 * nt2],     am[mt], bh[nt2][0], bh[nt2][2]);
                    mma16816(acc[mt][2 * nt2 + 1], am[mt], bh[nt2][1], bh[nt2][3]);
                }
        }
        __syncthreads();
    }

    // epilogue: store gelu(z) as 2 bf16 planes; max-z per candidate
    u32* scol = (u32*)smem;
    if (tid < 128) scol[tid] = 0u;
    __syncthreads();

    const size_t PL = (size_t)SS * NC;
#pragma unroll
    for (int mt = 0; mt < 2; mt++)
#pragma unroll
        for (int nt = 0; nt < 8; nt++) {
            int row = s0 + wm * 32 + mt * 16 + (lid >> 2);
            int col = n0 + wn * 64 + nt * 8 + 2 * (lid & 3);
            float g0 = gelu_f(acc[mt][nt][0]), g1 = gelu_f(acc[mt][nt][1]);
            float g2 = gelu_f(acc[mt][nt][2]), g3 = gelu_f(acc[mt][nt][3]);
            B2U h01, m01, h23, m23;
            split2(g0, h01.h[0], m01.h[0]); split2(g1, h01.h[1], m01.h[1]);
            split2(g2, h23.h[0], m23.h[0]); split2(g3, h23.h[1], m23.h[1]);
            size_t base = ((size_t)(b * 2) * SS + row) * NC + col;
            *(u32*)(g_PC + base)               = h01.u;
            *(u32*)(g_PC + base + PL)          = m01.u;
            *(u32*)(g_PC + base + 8 * NC)      = h23.u;
            *(u32*)(g_PC + base + PL + 8 * NC) = m23.u;
        }
#pragma unroll
    for (int nt = 0; nt < 8; nt++) {
        float m0 = fmaxf(fmaxf(acc[0][nt][0], acc[0][nt][2]), fmaxf(acc[1][nt][0], acc[1][nt][2]));
        float m1 = fmaxf(fmaxf(acc[0][nt][1], acc[0][nt][3]), fmaxf(acc[1][nt][1], acc[1][nt][3]));
#pragma unroll
        for (int mk = 4; mk < 32; mk <<= 1) {
            m0 = fmaxf(m0, __shfl_xor_sync(0xffffffffu, m0, mk));
            m1 = fmaxf(m1, __shfl_xor_sync(0xffffffffu, m1, mk));
        }
        if (lid < 4) {
            atomicMax(&scol[wn * 64 + nt * 8 + 2 * lid],     fenc(m0));
            atomicMax(&scol[wn * 64 + nt * 8 + 2 * lid + 1], fenc(m1));
        }
    }
    __syncthreads();
    if (tid < 128) atomicMax(&g_scoreEnc2[b * NC + n0 + tid], scol[tid]);
}

// ---------------- K6: exact rescore of 512 cands + top-256 ----------------
__global__ void k_rescore() {
    __shared__ ull key[NC];
    int b = blockIdx.x, tid = threadIdx.x;   // 256 threads
    for (int i = tid; i < NC; i += 256) {
        float z = fdec(g_scoreEnc2[b * NC + i]);
        int p = g_pidx512[b * NC + i];
        float sc = gelu_f(z) * g_sig[b * NP + p];
        key[i] = ((ull)fenc(sc) << 32) | (unsigned)i;
    }
    __syncthreads();
    for (int k = 2; k <= NC; k <<= 1) {
        for (int j = k >> 1; j > 0; j >>= 1) {
            for (int i = tid; i < NC; i += 256) {
                int ix = i ^ j;
                if (ix > i) {
                    ull x = key[i], y = key[ix];
                    bool desc = ((i & k) == 0);
                    if (desc ? (x < y) : (x > y)) { key[i] = y; key[ix] = x; }
                }
            }
            __syncthreads();
        }
    }
    if (tid < KSEL) {
        int slot = (int)(key[tid] & 0xffffffffu);
        g_cmap[b * KSEL + tid] = slot;
        g_pidx[b * KSEL + tid] = g_pidx512[b * NC + slot];
    }
}

// ---------------- K7: compact selected 256 columns of g_PC -> g_PA ----------------
__global__ void k_compact() {
    int blk = blockIdx.x;                 // b*SS + s
    int b = blk >> 11, s = blk & (SS - 1);
    int j = threadIdx.x;                  // 256
    int cm = g_cmap[b * KSEL + j];
    const size_t PLc = (size_t)SS * NC;
    const size_t PLa = (size_t)SS * KSEL;
    size_t src = ((size_t)(b * 2) * SS + s) * NC + cm;
    size_t dst = ((size_t)(b * 2) * SS + s) * KSEL + j;
    g_PA[dst]       = g_PC[src];
    g_PA[dst + PLa] = g_PC[src + PLc];
}

// ---------------- K8: gather + transpose + split proj rows -> g_Pr [sp][d][j] ----------------
__global__ void k_projsplit(const float* __restrict__ proj) {
    __shared__ float t[32][33];
    __shared__ int pj[32];
    int j0 = blockIdx.x * 32, d0 = blockIdx.y * 32, b = blockIdx.z;
    int tx = threadIdx.x, ty = threadIdx.y;
    if (ty == 0) pj[tx] = g_pidx[b * KSEL + j0 + tx];
    __syncthreads();
#pragma unroll
    for (int i = 0; i < 32; i += 8) {
        int p = pj[ty + i];
        t[ty + i][tx] = proj[(size_t)p * DM + d0 + tx];
    }
    __syncthreads();
    const size_t PL = (size_t)DM * KSEL;
#pragma unroll
    for (int i = 0; i < 32; i += 8) {
        float v = t[tx][ty + i];
        __nv_bfloat16 h, m;
        split2(v, h, m);
        size_t base = ((size_t)(b * 2) * DM + d0 + ty + i) * KSEL + j0 + tx;
        g_Pr[base]      = h;
        g_Pr[base + PL] = m;
    }
}

// ---------------- K9: final GEMM (HMMA 3-pass): out = PA @ Pr^T ----------------
__global__ __launch_bounds__(256)
void k_gemm3t(float* __restrict__ out) {
    extern __shared__ char smem[];
    const u32 sbase = smem_u32(smem);
    const int tid = threadIdx.x;
    const int wid = tid >> 5, lid = tid & 31;
    const int wm = wid & 3, wn = wid >> 2;
    const int b  = blockIdx.z;
    const int d0 = blockIdx.x * 128;
    const int s0 = blockIdx.y * 128;

    float acc[2][8][4];
#pragma unroll
    for (int i = 0; i < 2; i++)
#pragma unroll
        for (int j = 0; j < 8; j++)
#pragma unroll
            for (int r = 0; r < 4; r++) acc[i][j][r] = 0.0f;

    auto load_stage = [&](int ks, int buf) {
        const int k0 = ks * 32;
        u32 sg = sbase + buf * STGB4;
#pragma unroll
        for (int i = 0; i < 4; i++) {
            int idx = tid + i * 256;
            int sp = idx >> 9, rem = idx & 511;
            int r = rem >> 2, c = rem & 3;
            const __nv_bfloat16* g = g_PA + ((size_t)(b * 2 + sp) * SS + s0 + r) * KSEL + k0 + c * 8;
            cpasync16(sg + sp * PLANE + r * RPAD + c * 16, g);
        }
#pragma unroll
        for (int i = 0; i < 4; i++) {
            int idx = tid + i * 256;
            int sp = idx >> 9, rem = idx & 511;
            int r = rem >> 2, c = rem & 3;
            const __nv_bfloat16* g = g_Pr + ((size_t)(b * 2 + sp) * DM + d0 + r) * KSEL + k0 + c * 8;
            cpasync16(sg + 2 * PLANE + sp * PLANE + r * RPAD + c * 16, g);
        }
    };

    const u32 aoff = (u32)((wm * 32 + (lid & 15)) * RPAD + (lid >> 4) * 16);
    const u32 boff = (u32)((wn * 64 + (lid & 15)) * RPAD + (lid >> 4) * 16);

    load_stage(0, 0); CP_COMMIT();

#pragma unroll 1
    for (int ks = 0; ks < KSEL / 32; ks++) {
        int buf = ks & 1;
        if (ks < KSEL / 32 - 1) { load_stage(ks + 1, buf ^ 1); CP_COMMIT(); CP_WAIT(1); }
        else                    { CP_WAIT(0); }
        __syncthreads();
        u32 sA = sbase + buf * STGB4;
        u32 sB = sA + 2 * PLANE;
#pragma unroll
        for (int kk = 0; kk < 2; kk++) {
            u32 ah[2][4], am[2][4];
#pragma unroll
            for (int mt = 0; mt < 2; mt++) {
                ldsm4(ah[mt], sA + aoff + mt * (16 * RPAD) + kk * 32);
                ldsm4(am[mt], sA + PLANE + aoff + mt * (16 * RPAD) + kk * 32);
            }
            u32 bh[4][4], bm[4][4];
#pragma unroll
            for (int nt2 = 0; nt2 < 4; nt2++) {
                ldsm4(bh[nt2], sB + boff + nt2 * (16 * RPAD) + kk * 32);
                ldsm4(bm[nt2], sB + PLANE + boff + nt2 * (16 * RPAD) + kk * 32);
            }
#pragma unroll
            for (int mt = 0; mt < 2; mt++)
#pragma unroll
                for (int nt2 = 0; nt2 < 4; nt2++) {
                    mma16816(acc[mt][2 * nt2],     ah[mt], bh[nt2][0], bh[nt2][2]);
                    mma16816(acc[mt][2 * nt2 + 1], ah[mt], bh[nt2][1], bh[nt2][3]);
                    mma16816(acc[mt][2 * nt2],     ah[mt], bm[nt2][0], bm[nt2][2]);
                    mma16816(acc[mt][2 * nt2 + 1], ah[mt], bm[nt2][1], bm[nt2][3]);
                    mma16816(acc[mt][2 * nt2],     am[mt], bh[nt2][0], bh[nt2][2]);
                    mma16816(acc[mt][2 * nt2 + 1], am[mt], bh[nt2][1], bh[nt2][3]);
                }
        }
        __syncthreads();
    }
#pragma unroll
    for (int mt = 0; mt < 2; mt++)
#pragma unroll
        for (int nt = 0; nt < 8; nt++) {
            int row = s0 + wm * 32 + mt * 16 + (lid >> 2);
            int col = d0 + wn * 64 + nt * 8 + 2 * (lid & 3);
            float* po = out + ((size_t)b * SS + row) * DM + col;
            *(float2*)po            = make_float2(acc[mt][nt][0], acc[mt][nt][1]);
            *(float2*)(po + 8 * DM) = make_float2(acc[mt][nt][2], acc[mt][nt][3]);
        }
}

// ---------------- entry ----------------
extern "C" void kernel_launch(void* const* d_in, const int* in_sizes, int n_in,
                              void* d_out, int out_size) {
    const float* act  = (const float*)d_in[0];
    const int*   sidx = (const int*)d_in[1];
    int o = (n_in >= 9 && in_sizes[2] == 1) ? 3 : 2;
    const float* cw   = (const float*)d_in[o + 0];
    const float* proj = (const float*)d_in[o + 1];
    const float* w1   = (const float*)d_in[o + 2];
    const float* b1   = (const float*)d_in[o + 3];
    const float* w2   = (const float*)d_in[o + 4];
    const float* b2   = (const float*)d_in[o + 5];
    float* out = (float*)d_out;

    k_init<<<(BB * NP + 255) / 256, 256>>>();
    k_scatter<<<(BB * KIN + 255) / 256, 256>>>(sidx);
    k_splitA<<<(BB * SS * KIN / 4) / 256, 256>>>(act);
    k_gatherBh<<<NP, 256>>>(cw, sidx);

    cudaFuncSetAttribute(k_gemm1a, cudaFuncAttributeMaxDynamicSharedMemorySize, GSMEM2);
    k_gemm1a<<<dim3(NP / 128, SS / 128, BB), 256, GSMEM2>>>();

    k_hidden<<<HID, 256>>>(w1, b1);
    k_rel<<<NP / 8, 256>>>(w2, b2);
    k_topk512<<<BB, 512>>>();
    k_gatherB512<<<BB * NC, 256>>>(cw, sidx);

    cudaFuncSetAttribute(k_refine, cudaFuncAttributeMaxDynamicSharedMemorySize, GSMEM4);
    k_refine<<<dim3(NC / 128, SS / 128, BB), 256, GSMEM4>>>();

    k_rescore<<<BB, 256>>>();
    k_compact<<<BB * SS, 256>>>();
    k_projsplit<<<dim3(KSEL / 32, DM / 32, BB), dim3(32, 8)>>>(proj);

    cudaFuncSetAttribute(k_gemm3t, cudaFuncAttributeMaxDynamicSharedMemorySize, GSMEM4);
    k_gemm3t<<<dim3(DM / 128, SS / 128, BB), 256, GSMEM4>>>(out);
}

// round 5
// speedup vs baseline: 2.7475x; 1.0144x over previous
#include <cuda_runtime.h>
#include <cuda_bf16.h>

#define BB   8
#define SS   2048
#define KIN  512
#define NIN  2048
#define NP   4096
#define HID  4096
#define DM   1024
#define KSEL 256
#define NC   512

typedef unsigned long long ull;
typedef unsigned int u32;

// ---------------- scratch ----------------
__device__ __align__(256) __nv_bfloat16 g_Asp[(size_t)BB * 2 * SS * KIN];
__device__ __align__(256) __nv_bfloat16 g_Bh [(size_t)BB * NP * KIN];
__device__ __align__(256) __nv_bfloat16 g_Bc [(size_t)BB * 2 * NC * KIN];
__device__ __align__(256) __nv_bfloat16 g_PC [(size_t)BB * 2 * SS * NC];
__device__ __align__(256) __nv_bfloat16 g_PA [(size_t)BB * 2 * SS * KSEL];
__device__ __align__(256) __nv_bfloat16 g_Pr [(size_t)BB * 2 * DM * KSEL];
__device__ float    g_mask[BB * NIN];
__device__ float    g_h[BB * HID];
__device__ float    g_sig[BB * NP];
__device__ unsigned g_scoreEnc[BB * NP];
__device__ unsigned g_scoreEnc2[BB * NC];
__device__ float    g_fscore[BB * NP];
__device__ int      g_pidx512[BB * NC];
__device__ int      g_pidx[BB * KSEL];
__device__ int      g_cmap[BB * KSEL];

// ---------------- helpers ----------------
__device__ __forceinline__ unsigned fenc(float f) {
    unsigned u = __float_as_uint(f);
    return (u & 0x80000000u) ? ~u : (u | 0x80000000u);
}
__device__ __forceinline__ float fdec(unsigned u) {
    return __uint_as_float((u & 0x80000000u) ? (u & 0x7fffffffu) : ~u);
}
__device__ __forceinline__ float gelu_f(float x) {
    return 0.5f * x * (1.0f + erff(x * 0.70710678118654752f));
}
__device__ __forceinline__ u32 smem_u32(const void* p) {
    u32 a; asm("{ .reg .u64 t; cvta.to.shared.u64 t, %1; cvt.u32.u64 %0, t; }" : "=r"(a) : "l"(p));
    return a;
}
__device__ __forceinline__ void split2(float a, __nv_bfloat16& h, __nv_bfloat16& m) {
    h = __float2bfloat16(a);
    m = __float2bfloat16(a - __bfloat162float(h));
}

// ---------------- mma.sync / ldmatrix / cp.async ----------------
__device__ __forceinline__ void mma16816(float* d, const u32* a, u32 b0, u32 b1) {
    asm volatile("mma.sync.aligned.m16n8k16.row.col.f32.bf16.bf16.f32 "
        "{%0,%1,%2,%3}, {%4,%5,%6,%7}, {%8,%9}, {%0,%1,%2,%3};"
        : "+f"(d[0]), "+f"(d[1]), "+f"(d[2]), "+f"(d[3])
        : "r"(a[0]), "r"(a[1]), "r"(a[2]), "r"(a[3]), "r"(b0), "r"(b1));
}
__device__ __forceinline__ void ldsm4(u32* r, u32 addr) {
    asm volatile("ldmatrix.sync.aligned.m8n8.x4.shared.b16 {%0,%1,%2,%3}, [%4];"
        : "=r"(r[0]), "=r"(r[1]), "=r"(r[2]), "=r"(r[3]) : "r"(addr));
}
__device__ __forceinline__ void cpasync16(u32 dst, const void* src) {
    asm volatile("cp.async.cg.shared.global [%0], [%1], 16;" :: "r"(dst), "l"(src));
}
#define CP_COMMIT() asm volatile("cp.async.commit_group;" ::: "memory")
#define CP_WAIT(n)  asm volatile("cp.async.wait_group %0;" :: "n"(n) : "memory")

#define RPAD   80
#define PLANE  (128 * RPAD)          // 10240
#define BPLANE (256 * RPAD)          // 20480
#define STGB4  (4 * PLANE)
#define GSMEM4 (2 * STGB4)           // 81920
#define STG1   (PLANE + BPLANE)      // 30720
#define GSMEM1 (2 * STG1)            // 61440

// ---------------- init kernels ----------------
__global__ void k_initMask() {
    int t = blockIdx.x * blockDim.x + threadIdx.x;
    if (t < BB * NIN) g_mask[t] = 0.0f;
}
__global__ void k_initScore() {
    int t = blockIdx.x * blockDim.x + threadIdx.x;
    if (t < BB * NP)  g_scoreEnc[t] = 0u;
    if (t < BB * NC)  g_scoreEnc2[t] = 0u;
}
__global__ void k_scatter(const int* __restrict__ sidx) {
    int t = blockIdx.x * blockDim.x + threadIdx.x;
    if (t < BB * KIN) {
        int b = t >> 9;
        g_mask[b * NIN + sidx[t]] = 1.0f;
    }
}

// ---------------- split A into 2 bf16 planes ----------------
union B4U { __nv_bfloat16 h[4]; ull u; };
union B2U { __nv_bfloat16 h[2]; u32 u; };

__global__ void k_splitA(const float* __restrict__ act) {
    size_t t = (size_t)blockIdx.x * 256 + threadIdx.x;
    size_t bs = t >> 7;
    int k4 = (int)(t & 127);
    int b = (int)(bs >> 11), s = (int)(bs & 2047);
    float4 v = ((const float4*)act)[t];
    float vv[4] = { v.x, v.y, v.z, v.w };
    B4U hh, mm;
#pragma unroll
    for (int i = 0; i < 4; i++) split2(vv[i], hh.h[i], mm.h[i]);
    const size_t PL = (size_t)SS * KIN;
    size_t base = ((size_t)(b * 2) * SS + s) * KIN + k4 * 4;
    *(ull*)(g_Asp + base)      = hh.u;
    *(ull*)(g_Asp + base + PL) = mm.u;
}

// ---------------- gather B h-plane (full 4096 rows) ----------------
__global__ void k_gatherBh(const float* __restrict__ cw, const int* __restrict__ sidx) {
    __shared__ float row[NIN];
    __shared__ int sidxS[BB * KIN / 8];   // staged per-b below
    int p = blockIdx.x, tid = threadIdx.x;
    for (int i = tid; i < NIN; i += 256) row[i] = cw[(size_t)p * NIN + i];
    __syncthreads();
#pragma unroll 1
    for (int b = 0; b < BB; b++) {
        if (tid < 256) ((int2*)sidxS)[tid] = ((const int2*)(sidx + b * KIN))[tid];
        __syncthreads();
        int k = tid * 2;
        int i0 = sidxS[k], i1 = sidxS[k + 1];
        B2U hh;
        hh.h[0] = __float2bfloat16(row[i0]);
        hh.h[1] = __float2bfloat16(row[i1]);
        *(u32*)(g_Bh + ((size_t)b * NP + p) * KIN + k) = hh.u;
        __syncthreads();
    }
}

// ---------------- gather B splits for 512 candidates ----------------
__global__ void k_gatherB512(const float* __restrict__ cw, const int* __restrict__ sidx) {
    __shared__ float row[NIN];
    int blk = blockIdx.x;
    int b = blk >> 9, j = blk & (NC - 1);
    int tid = threadIdx.x;
    int p = g_pidx512[b * NC + j];
    for (int i = tid; i < NIN; i += 256) row[i] = cw[(size_t)p * NIN + i];
    __syncthreads();
    int k = tid * 2;
    int i0 = sidx[b * KIN + k], i1 = sidx[b * KIN + k + 1];
    B2U hh, mm;
    split2(row[i0], hh.h[0], mm.h[0]);
    split2(row[i1], hh.h[1], mm.h[1]);
    const size_t PL = (size_t)NC * KIN;
    size_t base = ((size_t)(b * 2) * NC + j) * KIN + k;
    *(u32*)(g_Bc + base)      = hh.u;
    *(u32*)(g_Bc + base + PL) = mm.u;
}

// ---------------- K1a: approx score GEMM, 128x256 tile ----------------
__global__ __launch_bounds__(256)
void k_gemm1a() {
    extern __shared__ char smem[];
    const u32 sbase = smem_u32(smem);
    const int tid = threadIdx.x;
    const int wid = tid >> 5, lid = tid & 31;
    const int wm = wid & 3, wn = wid >> 2;       // warp tile 32 x 128
    const int b  = blockIdx.z;
    const int p0 = blockIdx.x * 256;
    const int s0 = blockIdx.y * 128;

    float acc[2][16][4];
#pragma unroll
    for (int i = 0; i < 2; i++)
#pragma unroll
        for (int j = 0; j < 16; j++)
#pragma unroll
            for (int r = 0; r < 4; r++) acc[i][j][r] = 0.0f;

    auto load_stage = [&](int ks, int buf) {
        const int k0 = ks * 32;
        u32 sgA = sbase + buf * STG1;
        u32 sgB = sgA + PLANE;
#pragma unroll
        for (int i = 0; i < 2; i++) {   // A h-plane: 512 chunks
            int idx = tid + i * 256;
            int r = idx >> 2, c = idx & 3;
            const __nv_bfloat16* g = g_Asp + ((size_t)(b * 2) * SS + s0 + r) * KIN + k0 + c * 8;
            cpasync16(sgA + r * RPAD + c * 16, g);
        }
#pragma unroll
        for (int i = 0; i < 4; i++) {   // B h-plane: 1024 chunks (256 rows)
            int idx = tid + i * 256;
            int r = idx >> 2, c = idx & 3;
            const __nv_bfloat16* g = g_Bh + ((size_t)b * NP + p0 + r) * KIN + k0 + c * 8;
            cpasync16(sgB + r * RPAD + c * 16, g);
        }
    };

    const u32 aoff = (u32)((wm * 32 + (lid & 15)) * RPAD + (lid >> 4) * 16);
    const u32 boff = (u32)((wn * 128 + (lid & 15)) * RPAD + (lid >> 4) * 16);

    load_stage(0, 0); CP_COMMIT();

#pragma unroll 1
    for (int ks = 0; ks < KIN / 32; ks++) {
        int buf = ks & 1;
        if (ks < KIN / 32 - 1) { load_stage(ks + 1, buf ^ 1); CP_COMMIT(); CP_WAIT(1); }
        else                   { CP_WAIT(0); }
        __syncthreads();
        u32 sA = sbase + buf * STG1;
        u32 sB = sA + PLANE;
#pragma unroll
        for (int kk = 0; kk < 2; kk++) {
            u32 ah[2][4];
#pragma unroll
            for (int mt = 0; mt < 2; mt++)
                ldsm4(ah[mt], sA + aoff + mt * (16 * RPAD) + kk * 32);
            u32 bh[8][4];
#pragma unroll
            for (int q = 0; q < 8; q++)
                ldsm4(bh[q], sB + boff + q * (16 * RPAD) + kk * 32);
#pragma unroll
            for (int mt = 0; mt < 2; mt++)
#pragma unroll
                for (int q = 0; q < 8; q++) {
                    mma16816(acc[mt][2 * q],     ah[mt], bh[q][0], bh[q][2]);
                    mma16816(acc[mt][2 * q + 1], ah[mt], bh[q][1], bh[q][3]);
                }
        }
        __syncthreads();
    }

    // per-column max of z over the 128 rows
    u32* scol = (u32*)smem;
    if (tid < 256) scol[tid] = 0u;
    __syncthreads();
#pragma unroll
    for (int nt = 0; nt < 16; nt++) {
        float m0 = fmaxf(fmaxf(acc[0][nt][0], acc[0][nt][2]), fmaxf(acc[1][nt][0], acc[1][nt][2]));
        float m1 = fmaxf(fmaxf(acc[0][nt][1], acc[0][nt][3]), fmaxf(acc[1][nt][1], acc[1][nt][3]));
#pragma unroll
        for (int mk = 4; mk < 32; mk <<= 1) {
            m0 = fmaxf(m0, __shfl_xor_sync(0xffffffffu, m0, mk));
            m1 = fmaxf(m1, __shfl_xor_sync(0xffffffffu, m1, mk));
        }
        if (lid < 4) {
            atomicMax(&scol[wn * 128 + nt * 8 + 2 * lid],     fenc(m0));
            atomicMax(&scol[wn * 128 + nt * 8 + 2 * lid + 1], fenc(m1));
        }
    }
    __syncthreads();
    if (tid < 256) atomicMax(&g_scoreEnc[b * NP + p0 + tid], scol[tid]);
}

// ---------------- K2: hidden MLP ----------------
__global__ void k_hidden(const float* __restrict__ w1, const float* __restrict__ b1) {
    int j = blockIdx.x;
    int tid = threadIdx.x;
    const float* wr = w1 + (size_t)j * NIN;
    float acc[BB];
#pragma unroll
    for (int b = 0; b < BB; b++) acc[b] = 0.0f;
    for (int n = tid; n < NIN; n += 256) {
        float w = wr[n];
#pragma unroll
        for (int b = 0; b < BB; b++) acc[b] += w * g_mask[b * NIN + n];
    }
    __shared__ float red[BB][256];
#pragma unroll
    for (int b = 0; b < BB; b++) red[b][tid] = acc[b];
    __syncthreads();
    for (int s1 = 128; s1 > 0; s1 >>= 1) {
        if (tid < s1) {
#pragma unroll
            for (int b = 0; b < BB; b++) red[b][tid] += red[b][tid + s1];
        }
        __syncthreads();
    }
    if (tid < BB) g_h[tid * HID + j] = gelu_f(red[tid][0] + b1[j]);
}

// ---------------- K3a: relevance -> sigmoid only (independent of gemm1a) ----------------
__global__ void k_relsig(const float* __restrict__ w2, const float* __restrict__ b2) {
    int warp = threadIdx.x >> 5, lane = threadIdx.x & 31;
    int p = blockIdx.x * 8 + warp;
    const float* wr = w2 + (size_t)p * HID;
    float acc[BB];
#pragma unroll
    for (int b = 0; b < BB; b++) acc[b] = 0.0f;
    for (int j = lane; j < HID; j += 32) {
        float w = wr[j];
#pragma unroll
        for (int b = 0; b < BB; b++) acc[b] += w * g_h[b * HID + j];
    }
#pragma unroll
    for (int o = 16; o > 0; o >>= 1)
#pragma unroll
        for (int b = 0; b < BB; b++) acc[b] += __shfl_down_sync(0xffffffffu, acc[b], o);
    if (lane == 0) {
#pragma unroll
        for (int b = 0; b < BB; b++) {
            float rel = acc[b] + b2[p];
            g_sig[b * NP + p] = 1.0f / (1.0f + expf(-rel));
        }
    }
}

// ---------------- K3b: join — approx final scores ----------------
__global__ void k_fscore() {
    int t = blockIdx.x * 256 + threadIdx.x;
    g_fscore[t] = gelu_f(fdec(g_scoreEnc[t])) * g_sig[t];
}

// ---------------- K4: approx top-512 via bitonic (1024 threads) ----------------
__global__ void k_topk512() {
    __shared__ ull key[NP];
    int b = blockIdx.x, tid = threadIdx.x;
    for (int i = tid; i < NP; i += 1024)
        key[i] = ((ull)fenc(g_fscore[b * NP + i]) << 32) | (unsigned)i;
    __syncthreads();
    for (int k = 2; k <= NP; k <<= 1) {
        for (int j = k >> 1; j > 0; j >>= 1) {
            for (int i = tid; i < NP; i += 1024) {
                int ix = i ^ j;
                if (ix > i) {
                    ull x = key[i], y = key[ix];
                    bool desc = ((i & k) == 0);
                    if (desc ? (x < y) : (x > y)) { key[i] = y; key[ix] = x; }
                }
            }
            __syncthreads();
        }
    }
    if (tid < NC) g_pidx512[b * NC + tid] = (int)(key[tid] & 0xffffffffu);
}

// ---------------- K5: refine — exact 3-pass z for 512 cands ----------------
__global__ __launch_bounds__(256)
void k_refine() {
    extern __shared__ char smem[];
    const u32 sbase = smem_u32(smem);
    const int tid = threadIdx.x;
    const int wid = tid >> 5, lid = tid & 31;
    const int wm = wid & 3, wn = wid >> 2;
    const int b  = blockIdx.z;
    const int n0 = blockIdx.x * 128;
    const int s0 = blockIdx.y * 128;

    float acc[2][8][4];
#pragma unroll
    for (int i = 0; i < 2; i++)
#pragma unroll
        for (int j = 0; j < 8; j++)
#pragma unroll
            for (int r = 0; r < 4; r++) acc[i][j][r] = 0.0f;

    auto load_stage = [&](int ks, int buf) {
        const int k0 = ks * 32;
        u32 sg = sbase + buf * STGB4;
#pragma unroll
        for (int i = 0; i < 4; i++) {
            int idx = tid + i * 256;
            int sp = idx >> 9, rem = idx & 511;
            int r = rem >> 2, c = rem & 3;
            const __nv_bfloat16* g = g_Asp + ((size_t)(b * 2 + sp) * SS + s0 + r) * KIN + k0 + c * 8;
            cpasync16(sg + sp * PLANE + r * RPAD + c * 16, g);
        }
#pragma unroll
        for (int i = 0; i < 4; i++) {
            int idx = tid + i * 256;
            int sp = idx >> 9, rem = idx & 511;
            int r = rem >> 2, c = rem & 3;
            const __nv_bfloat16* g = g_Bc + ((size_t)(b * 2 + sp) * NC + n0 + r) * KIN + k0 + c * 8;
            cpasync16(sg + 2 * PLANE + sp * PLANE + r * RPAD + c * 16, g);
        }
    };

    const u32 aoff = (u32)((wm * 32 + (lid & 15)) * RPAD + (lid >> 4) * 16);
    const u32 boff = (u32)((wn * 64 + (lid & 15)) * RPAD + (lid >> 4) * 16);

    load_stage(0, 0); CP_COMMIT();

#pragma unroll 1
    for (int ks = 0; ks < KIN / 32; ks++) {
        int buf = ks & 1;
        if (ks < KIN / 32 - 1) { load_stage(ks + 1, buf ^ 1); CP_COMMIT(); CP_WAIT(1); }
        else                   { CP_WAIT(0); }
        __syncthreads();
        u32 sA = sbase + buf * STGB4;
        u32 sB = sA + 2 * PLANE;
#pragma unroll
        for (int kk = 0; kk < 2; kk++) {
            u32 ah[2][4], am[2][4];
#pragma unroll
            for (int mt = 0; mt < 2; mt++) {
                ldsm4(ah[mt], sA + aoff + mt * (16 * RPAD) + kk * 32);
                ldsm4(am[mt], sA + PLANE + aoff + mt * (16 * RPAD) + kk * 32);
            }
            u32 bh[4][4], bm[4][4];
#pragma unroll
            for (int nt2 = 0; nt2 < 4; nt2++) {
                ldsm4(bh[nt2], sB + boff + nt2 * (16 * RPAD) + kk * 32);
                ldsm4(bm[nt2], sB + PLANE + boff + nt2 * (16 * RPAD) + kk * 32);
            }
#pragma unroll
            for (int mt = 0; mt < 2; mt++)
#pragma unroll
                for (int nt2 = 0; nt2 < 4; nt2++) {
                    mma16816(acc[mt][2 * nt2],     ah[mt], bh[nt2][0], bh[nt2][2]);
                    mma16816(acc[mt][2 * nt2 + 1], ah[mt], bh[nt2][1], bh[nt2][3]);
                    mma16816(acc[mt][2 * nt2],     ah[mt], bm[nt2][0], bm[nt2][2]);
                    mma16816(acc[mt][2 * nt2 + 1], ah[mt], bm[nt2][1], bm[nt2][3]);
                    mma16816(acc[mt][2 * nt2],     am[mt], bh[nt2][0], bh[nt2][2]);
                    mma16816(acc[mt][2 * nt2 + 1], am[mt], bh[nt2][1], bh[nt2][3]);
                }
        }
        __syncthreads();
    }

    u32* scol = (u32*)smem;
    if (tid < 128) scol[tid] = 0u;
    __syncthreads();

    const size_t PL = (size_t)SS * NC;
#pragma unroll
    for (int mt = 0; mt < 2; mt++)
#pragma unroll
        for (int nt = 0; nt < 8; nt++) {
            int row = s0 + wm * 32 + mt * 16 + (lid >> 2);
            int col = n0 + wn * 64 + nt * 8 + 2 * (lid & 3);
            float g0 = gelu_f(acc[mt][nt][0]), g1 = gelu_f(acc[mt][nt][1]);
            float g2 = gelu_f(acc[mt][nt][2]), g3 = gelu_f(acc[mt][nt][3]);
            B2U h01, m01, h23, m23;
            split2(g0, h01.h[0], m01.h[0]); split2(g1, h01.h[1], m01.h[1]);
            split2(g2, h23.h[0], m23.h[0]); split2(g3, h23.h[1], m23.h[1]);
            size_t base = ((size_t)(b * 2) * SS + row) * NC + col;
            *(u32*)(g_PC + base)               = h01.u;
            *(u32*)(g_PC + base + PL)          = m01.u;
            *(u32*)(g_PC + base + 8 * NC)      = h23.u;
            *(u32*)(g_PC + base + PL + 8 * NC) = m23.u;
        }
#pragma unroll
    for (int nt = 0; nt < 8; nt++) {
        float m0 = fmaxf(fmaxf(acc[0][nt][0], acc[0][nt][2]), fmaxf(acc[1][nt][0], acc[1][nt][2]));
        float m1 = fmaxf(fmaxf(acc[0][nt][1], acc[0][nt][3]), fmaxf(acc[1][nt][1], acc[1][nt][3]));
#pragma unroll
        for (int mk = 4; mk < 32; mk <<= 1) {
            m0 = fmaxf(m0, __shfl_xor_sync(0xffffffffu, m0, mk));
            m1 = fmaxf(m1, __shfl_xor_sync(0xffffffffu, m1, mk));
        }
        if (lid < 4) {
            atomicMax(&scol[wn * 64 + nt * 8 + 2 * lid],     fenc(m0));
            atomicMax(&scol[wn * 64 + nt * 8 + 2 * lid + 1], fenc(m1));
        }
    }
    __syncthreads();
    if (tid < 128) atomicMax(&g_scoreEnc2[b * NC + n0 + tid], scol[tid]);
}

// ---------------- K6: exact rescore of 512 cands + top-256 ----------------
__global__ void k_rescore() {
    __shared__ ull key[NC];
    int b = blockIdx.x, tid = threadIdx.x;   // 512 threads
    if (tid < NC) {
        float z = fdec(g_scoreEnc2[b * NC + tid]);
        int p = g_pidx512[b * NC + tid];
        float sc = gelu_f(z) * g_sig[b * NP + p];
        key[tid] = ((ull)fenc(sc) << 32) | (unsigned)tid;
    }
    __syncthreads();
    for (int k = 2; k <= NC; k <<= 1) {
        for (int j = k >> 1; j > 0; j >>= 1) {
            int i = tid;
            int ix = i ^ j;
            if (ix > i && i < NC) {
                ull x = key[i], y = key[ix];
                bool desc = ((i & k) == 0);
                if (desc ? (x < y) : (x > y)) { key[i] = y; key[ix] = x; }
            }
            __syncthreads();
        }
    }
    if (tid < KSEL) {
        int slot = (int)(key[tid] & 0xffffffffu);
        g_cmap[b * KSEL + tid] = slot;
        g_pidx[b * KSEL + tid] = g_pidx512[b * NC + slot];
    }
}

// ---------------- K7: compact selected 256 columns ----------------
__global__ void k_compact() {
    int blk = blockIdx.x;
    int b = blk >> 11, s = blk & (SS - 1);
    int j = threadIdx.x;
    int cm = g_cmap[b * KSEL + j];
    const size_t PLc = (size_t)SS * NC;
    const size_t PLa = (size_t)SS * KSEL;
    size_t src = ((size_t)(b * 2) * SS + s) * NC + cm;
    size_t dst = ((size_t)(b * 2) * SS + s) * KSEL + j;
    g_PA[dst]       = g_PC[src];
    g_PA[dst + PLa] = g_PC[src + PLc];
}

// ---------------- K8: gather + transpose + split proj rows ----------------
__global__ void k_projsplit(const float* __restrict__ proj) {
    __shared__ float t[32][33];
    __shared__ int pj[32];
    int j0 = blockIdx.x * 32, d0 = blockIdx.y * 32, b = blockIdx.z;
    int tx = threadIdx.x, ty = threadIdx.y;
    if (ty == 0) pj[tx] = g_pidx[b * KSEL + j0 + tx];
    __syncthreads();
#pragma unroll
    for (int i = 0; i < 32; i += 8) {
        int p = pj[ty + i];
        t[ty + i][tx] = proj[(size_t)p * DM + d0 + tx];
    }
    __syncthreads();
    const size_t PL = (size_t)DM * KSEL;
#pragma unroll
    for (int i = 0; i < 32; i += 8) {
        float v = t[tx][ty + i];
        __nv_bfloat16 h, m;
        split2(v, h, m);
        size_t base = ((size_t)(b * 2) * DM + d0 + ty + i) * KSEL + j0 + tx;
        g_Pr[base]      = h;
        g_Pr[base + PL] = m;
    }
}

// ---------------- K9: final GEMM (HMMA 3-pass) ----------------
__global__ __launch_bounds__(256)
void k_gemm3t(float* __restrict__ out) {
    extern __shared__ char smem[];
    const u32 sbase = smem_u32(smem);
    const int tid = threadIdx.x;
    const int wid = tid >> 5, lid = tid & 31;
    const int wm = wid & 3, wn = wid >> 2;
    const int b  = blockIdx.z;
    const int d0 = blockIdx.x * 128;
    const int s0 = blockIdx.y * 128;

    float acc[2][8][4];
#pragma unroll
    for (int i = 0; i < 2; i++)
#pragma unroll
        for (int j = 0; j < 8; j++)
#pragma unroll
            for (int r = 0; r < 4; r++) acc[i][j][r] = 0.0f;

    auto load_stage = [&](int ks, int buf) {
        const int k0 = ks * 32;
        u32 sg = sbase + buf * STGB4;
#pragma unroll
        for (int i = 0; i < 4; i++) {
            int idx = tid + i * 256;
            int sp = idx >> 9, rem = idx & 511;
            int r = rem >> 2, c = rem & 3;
            const __nv_bfloat16* g = g_PA + ((size_t)(b * 2 + sp) * SS + s0 + r) * KSEL + k0 + c * 8;
            cpasync16(sg + sp * PLANE + r * RPAD + c * 16, g);
        }
#pragma unroll
        for (int i = 0; i < 4; i++) {
            int idx = tid + i * 256;
            int sp = idx >> 9, rem = idx & 511;
            int r = rem >> 2, c = rem & 3;
            const __nv_bfloat16* g = g_Pr + ((size_t)(b * 2 + sp) * DM + d0 + r) * KSEL + k0 + c * 8;
            cpasync16(sg + 2 * PLANE + sp * PLANE + r * RPAD + c * 16, g);
        }
    };

    const u32 aoff = (u32)((wm * 32 + (lid & 15)) * RPAD + (lid >> 4) * 16);
    const u32 boff = (u32)((wn * 64 + (lid & 15)) * RPAD + (lid >> 4) * 16);

    load_stage(0, 0); CP_COMMIT();

#pragma unroll 1
    for (int ks = 0; ks < KSEL / 32; ks++) {
        int buf = ks & 1;
        if (ks < KSEL / 32 - 1) { load_stage(ks + 1, buf ^ 1); CP_COMMIT(); CP_WAIT(1); }
        else                    { CP_WAIT(0); }
        __syncthreads();
        u32 sA = sbase + buf * STGB4;
        u32 sB = sA + 2 * PLANE;
#pragma unroll
        for (int kk = 0; kk < 2; kk++) {
            u32 ah[2][4], am[2][4];
#pragma unroll
            for (int mt = 0; mt < 2; mt++) {
                ldsm4(ah[mt], sA + aoff + mt * (16 * RPAD) + kk * 32);
                ldsm4(am[mt], sA + PLANE + aoff + mt * (16 * RPAD) + kk * 32);
            }
            u32 bh[4][4], bm[4][4];
#pragma unroll
            for (int nt2 = 0; nt2 < 4; nt2++) {
                ldsm4(bh[nt2], sB + boff + nt2 * (16 * RPAD) + kk * 32);
                ldsm4(bm[nt2], sB + PLANE + boff + nt2 * (16 * RPAD) + kk * 32);
            }
#pragma unroll
            for (int mt = 0; mt < 2; mt++)
#pragma unroll
                for (int nt2 = 0; nt2 < 4; nt2++) {
                    mma16816(acc[mt][2 * nt2],     ah[mt], bh[nt2][0], bh[nt2][2]);
                    mma16816(acc[mt][2 * nt2 + 1], ah[mt], bh[nt2][1], bh[nt2][3]);
                    mma16816(acc[mt][2 * nt2],     ah[mt], bm[nt2][0], bm[nt2][2]);
                    mma16816(acc[mt][2 * nt2 + 1], ah[mt], bm[nt2][1], bm[nt2][3]);
                    mma16816(acc[mt][2 * nt2],     am[mt], bh[nt2][0], bh[nt2][2]);
                    mma16816(acc[mt][2 * nt2 + 1], am[mt], bh[nt2][1], bh[nt2][3]);
                }
        }
        __syncthreads();
    }
#pragma unroll
    for (int mt = 0; mt < 2; mt++)
#pragma unroll
        for (int nt = 0; nt < 8; nt++) {
            int row = s0 + wm * 32 + mt * 16 + (lid >> 2);
            int col = d0 + wn * 64 + nt * 8 + 2 * (lid & 3);
            float* po = out + ((size_t)b * SS + row) * DM + col;
            *(float2*)po            = make_float2(acc[mt][nt][0], acc[mt][nt][1]);
            *(float2*)(po + 8 * DM) = make_float2(acc[mt][nt][2], acc[mt][nt][3]);
        }
}

// ---------------- entry (multi-stream fork/join for graph overlap) ----------------
extern "C" void kernel_launch(void* const* d_in, const int* in_sizes, int n_in,
                              void* d_out, int out_size) {
    const float* act  = (const float*)d_in[0];
    const int*   sidx = (const int*)d_in[1];
    int o = (n_in >= 9 && in_sizes[2] == 1) ? 3 : 2;
    const float* cw   = (const float*)d_in[o + 0];
    const float* proj = (const float*)d_in[o + 1];
    const float* w1   = (const float*)d_in[o + 2];
    const float* b1   = (const float*)d_in[o + 3];
    const float* w2   = (const float*)d_in[o + 4];
    const float* b2   = (const float*)d_in[o + 5];
    float* out = (float*)d_out;

    static cudaStream_t s1 = nullptr;
    static cudaEvent_t ev0 = nullptr, ev1 = nullptr, ev2 = nullptr, ev3 = nullptr;
    if (s1 == nullptr) {
        cudaStreamCreateWithFlags(&s1, cudaStreamNonBlocking);
        cudaEventCreateWithFlags(&ev0, cudaEventDisableTiming);
        cudaEventCreateWithFlags(&ev1, cudaEventDisableTiming);
        cudaEventCreateWithFlags(&ev2, cudaEventDisableTiming);
        cudaEventCreateWithFlags(&ev3, cudaEventDisableTiming);
        cudaFuncSetAttribute(k_gemm1a, cudaFuncAttributeMaxDynamicSharedMemorySize, GSMEM1);
        cudaFuncSetAttribute(k_refine, cudaFuncAttributeMaxDynamicSharedMemorySize, GSMEM4);
        cudaFuncSetAttribute(k_gemm3t, cudaFuncAttributeMaxDynamicSharedMemorySize, GSMEM4);
    }

    // fork: MLP chain on s1 (independent of gemm1a chain)
    cudaEventRecord(ev0, 0);
    cudaStreamWaitEvent(s1, ev0, 0);
    k_initMask<<<(BB * NIN + 255) / 256, 256, 0, s1>>>();
    k_scatter<<<(BB * KIN + 255) / 256, 256, 0, s1>>>(sidx);
    k_hidden<<<HID, 256, 0, s1>>>(w1, b1);
    k_relsig<<<NP / 8, 256, 0, s1>>>(w2, b2);
    cudaEventRecord(ev1, s1);

    // main chain
    k_initScore<<<(BB * NP + 255) / 256, 256>>>();
    k_splitA<<<(BB * SS * KIN / 4) / 256, 256>>>(act);
    k_gatherBh<<<NP, 256>>>(cw, sidx);
    k_gemm1a<<<dim3(NP / 256, SS / 128, BB), 256, GSMEM1>>>();

    // join: needs g_sig + g_scoreEnc
    cudaStreamWaitEvent(0, ev1, 0);
    k_fscore<<<BB * NP / 256, 256>>>();
    k_topk512<<<BB, 1024>>>();
    k_gatherB512<<<BB * NC, 256>>>(cw, sidx);
    k_refine<<<dim3(NC / 128, SS / 128, BB), 256, GSMEM4>>>();
    k_rescore<<<BB, 512>>>();

    // fork: projsplit on s1, compact on main
    cudaEventRecord(ev2, 0);
    cudaStreamWaitEvent(s1, ev2, 0);
    k_projsplit<<<dim3(KSEL / 32, DM / 32, BB), dim3(32, 8), 0, s1>>>(proj);
    cudaEventRecord(ev3, s1);
    k_compact<<<BB * SS, 256>>>();
    cudaStreamWaitEvent(0, ev3, 0);

    k_gemm3t<<<dim3(DM / 128, SS / 128, BB), 256, GSMEM4>>>(out);
}